// round 1
// baseline (speedup 1.0000x reference)
#include <cuda_runtime.h>
#include <math.h>

#define NN 50000
#define EE 800000
#define ET (EE + NN)      // 850000 edges incl. self loops
#define HH 4
#define CC 64
#define HC 256            // HH*CC
#define NEG 0.2f
#define EPS_SM 1e-16f
#define EPS_BN 1e-5f

// ---------------- scratch (device globals: allocation-free) ----------------
__device__ float g_h[NN * HC];      // per-layer transformed features [N, H, C]
__device__ float g_al[NN * HH];     // src attention term per node
__device__ float g_ar[NN * HH];     // dst attention term per node
__device__ float g_m[NN * HH];      // segment max
__device__ float g_den[NN * HH];    // segment sum of exp
__device__ float g_p[ET * HH];      // edge logits, then exp numerators
__device__ float g_acc[NN * CC];    // aggregated output (head-mean)
__device__ float g_feat[NN * CC];   // post-BN/ReLU features (next layer input)
__device__ float g_bnsum[CC];
__device__ float g_bnsq[CC];

// ---------------- helpers ----------------
__device__ __forceinline__ float lrelu(float v) {
    return v > 0.f ? v : NEG * v;
}

__device__ __forceinline__ void atomicMaxF(float* addr, float val) {
    int* a = (int*)addr;
    int old = *a;
    while (__int_as_float(old) < val) {
        int prev = atomicCAS(a, old, __float_as_int(val));
        if (prev == old) break;
        old = prev;
    }
}

// ---------------- GEMM: C[N,256] = A[N,K] * B[K,256], writes g_h -----------
// BM=64, BN=64, BK=16, 16x16 threads, 4x4 microtile per thread.
template <int K>
__global__ __launch_bounds__(256) void gemm_kernel(
    const float* __restrict__ A, const float* __restrict__ B, int nrows)
{
    __shared__ float As[16][64];
    __shared__ float Bs[16][64];

    const int row0 = blockIdx.y * 64;
    const int bn0  = blockIdx.x * 64;
    const int tid  = threadIdx.y * 16 + threadIdx.x;
    const int tx   = threadIdx.x;   // col group
    const int ty   = threadIdx.y;   // row group

    float acc[4][4];
#pragma unroll
    for (int i = 0; i < 4; i++)
#pragma unroll
        for (int j = 0; j < 4; j++) acc[i][j] = 0.f;

    for (int k0 = 0; k0 < K; k0 += 16) {
        // load A tile [64 rows x 16 k]
#pragma unroll
        for (int i = 0; i < 4; i++) {
            int r = i * 16 + (tid >> 4);
            int c = tid & 15;
            int gr = row0 + r;
            As[c][r] = (gr < nrows) ? A[(size_t)gr * K + k0 + c] : 0.f;
        }
        // load B tile [16 k x 64 cols]
#pragma unroll
        for (int i = 0; i < 4; i++) {
            int idx = i * 256 + tid;
            int kr = idx >> 6;
            int nc = idx & 63;
            Bs[kr][nc] = B[(size_t)(k0 + kr) * 256 + bn0 + nc];
        }
        __syncthreads();

#pragma unroll
        for (int kk = 0; kk < 16; kk++) {
            float4 a4 = *(const float4*)&As[kk][ty * 4];
            float4 b4 = *(const float4*)&Bs[kk][tx * 4];
            float av[4] = {a4.x, a4.y, a4.z, a4.w};
            float bv[4] = {b4.x, b4.y, b4.z, b4.w};
#pragma unroll
            for (int i = 0; i < 4; i++)
#pragma unroll
                for (int j = 0; j < 4; j++) acc[i][j] = fmaf(av[i], bv[j], acc[i][j]);
        }
        __syncthreads();
    }

#pragma unroll
    for (int i = 0; i < 4; i++) {
        int gr = row0 + ty * 4 + i;
        if (gr < nrows) {
            float4 v = make_float4(acc[i][0], acc[i][1], acc[i][2], acc[i][3]);
            *(float4*)&g_h[(size_t)gr * 256 + bn0 + tx * 4] = v;
        }
    }
}

// ---------------- attention coefficients: one warp per (n,h) ---------------
__global__ __launch_bounds__(256) void attn_kernel(
    const float* __restrict__ asrc, const float* __restrict__ adst)
{
    int widx = (blockIdx.x * blockDim.x + threadIdx.x) >> 5;
    int lane = threadIdx.x & 31;
    if (widx >= NN * HH) return;
    int n = widx >> 2;
    int h = widx & 3;
    const float* hp = g_h + (size_t)n * HC + h * CC;
    float h0 = hp[lane], h1 = hp[lane + 32];
    float sl = h0 * asrc[h * CC + lane] + h1 * asrc[h * CC + lane + 32];
    float sr = h0 * adst[h * CC + lane] + h1 * adst[h * CC + lane + 32];
#pragma unroll
    for (int o = 16; o; o >>= 1) {
        sl += __shfl_down_sync(0xffffffffu, sl, o);
        sr += __shfl_down_sync(0xffffffffu, sr, o);
    }
    if (lane == 0) {
        g_al[widx] = sl;
        g_ar[widx] = sr;
    }
}

// ---------------- per-layer init: m=-inf, den=0, bn accumulators=0 ---------
__global__ void init_kernel()
{
    int i = blockIdx.x * blockDim.x + threadIdx.x;
    if (i < NN * HH) {
        g_m[i] = -INFINITY;
        g_den[i] = 0.f;
    }
    if (i < CC) {
        g_bnsum[i] = 0.f;
        g_bnsq[i] = 0.f;
    }
}

// ---------------- edge pass 1: logits + segment max ------------------------
__global__ __launch_bounds__(256) void edge_logit_kernel(const int* __restrict__ ei)
{
    int e = blockIdx.x * blockDim.x + threadIdx.x;
    if (e >= ET) return;
    int s, d;
    if (e < EE) { s = ei[e]; d = ei[EE + e]; }
    else        { s = d = e - EE; }
    float4 al = *(const float4*)(g_al + (size_t)s * 4);
    float4 ar = *(const float4*)(g_ar + (size_t)d * 4);
    float v0 = lrelu(al.x + ar.x);
    float v1 = lrelu(al.y + ar.y);
    float v2 = lrelu(al.z + ar.z);
    float v3 = lrelu(al.w + ar.w);
    *(float4*)(g_p + (size_t)e * 4) = make_float4(v0, v1, v2, v3);
    atomicMaxF(&g_m[d * 4 + 0], v0);
    atomicMaxF(&g_m[d * 4 + 1], v1);
    atomicMaxF(&g_m[d * 4 + 2], v2);
    atomicMaxF(&g_m[d * 4 + 3], v3);
}

// ---------------- edge pass 2: exp + segment sum ---------------------------
__global__ __launch_bounds__(256) void edge_exp_kernel(const int* __restrict__ ei)
{
    int e = blockIdx.x * blockDim.x + threadIdx.x;
    if (e >= ET) return;
    int d = (e < EE) ? ei[EE + e] : (e - EE);
    float4 ev = *(const float4*)(g_p + (size_t)e * 4);
    float4 mv = *(const float4*)(g_m + (size_t)d * 4);
    float p0 = expf(ev.x - mv.x);
    float p1 = expf(ev.y - mv.y);
    float p2 = expf(ev.z - mv.z);
    float p3 = expf(ev.w - mv.w);
    *(float4*)(g_p + (size_t)e * 4) = make_float4(p0, p1, p2, p3);
    atomicAdd(&g_den[d * 4 + 0], p0);
    atomicAdd(&g_den[d * 4 + 1], p1);
    atomicAdd(&g_den[d * 4 + 2], p2);
    atomicAdd(&g_den[d * 4 + 3], p3);
}

// ---------------- edge pass 3: weighted scatter (warp per edge) ------------
__global__ __launch_bounds__(256) void edge_scatter_kernel(
    const int* __restrict__ ei, float* __restrict__ out)
{
    int widx = (blockIdx.x * blockDim.x + threadIdx.x) >> 5;
    int lane = threadIdx.x & 31;
    if (widx >= ET) return;
    int s, d;
    if (widx < EE) { s = ei[widx]; d = ei[EE + widx]; }
    else           { s = d = widx - EE; }
    float4 p   = *(const float4*)(g_p + (size_t)widx * 4);
    float4 den = *(const float4*)(g_den + (size_t)d * 4);
    float w0 = p.x / (den.x + EPS_SM) * 0.25f;
    float w1 = p.y / (den.y + EPS_SM) * 0.25f;
    float w2 = p.z / (den.z + EPS_SM) * 0.25f;
    float w3 = p.w / (den.w + EPS_SM) * 0.25f;
    const float* hs = g_h + (size_t)s * HC;
#pragma unroll
    for (int half = 0; half < 2; half++) {
        int c = lane + half * 32;
        float v = hs[c] * w0 + hs[64 + c] * w1 + hs[128 + c] * w2 + hs[192 + c] * w3;
        atomicAdd(out + (size_t)d * CC + c, v);
    }
}

// ---------------- BN statistics over g_acc ---------------------------------
__global__ __launch_bounds__(256) void bn_stats_kernel()
{
    __shared__ float ss[CC], sq[CC];
    if (threadIdx.x < CC) { ss[threadIdx.x] = 0.f; sq[threadIdx.x] = 0.f; }
    __syncthreads();
    for (int i = blockIdx.x * blockDim.x + threadIdx.x; i < NN * CC;
         i += gridDim.x * blockDim.x) {
        float x = g_acc[i];
        int c = i & 63;
        atomicAdd(&ss[c], x);
        atomicAdd(&sq[c], x * x);
    }
    __syncthreads();
    if (threadIdx.x < CC) {
        atomicAdd(&g_bnsum[threadIdx.x], ss[threadIdx.x]);
        atomicAdd(&g_bnsq[threadIdx.x], sq[threadIdx.x]);
    }
}

// ---------------- BN apply + ReLU: g_acc -> g_feat -------------------------
// (GAT bias omitted: it cancels exactly inside BatchNorm.)
__global__ __launch_bounds__(256) void bn_apply_kernel(
    const float* __restrict__ gam, const float* __restrict__ bet)
{
    int i = blockIdx.x * blockDim.x + threadIdx.x;
    if (i >= NN * CC) return;
    int c = i & 63;
    const float inv_n = 1.f / (float)NN;
    float mu = g_bnsum[c] * inv_n;
    float var = g_bnsq[c] * inv_n - mu * mu;
    float y = (g_acc[i] - mu) * rsqrtf(var + EPS_BN) * gam[c] + bet[c];
    g_feat[i] = fmaxf(y, 0.f);
}

// ---------------- final bias add -------------------------------------------
__global__ __launch_bounds__(256) void bias_kernel(float* __restrict__ o,
                                                   const float* __restrict__ b)
{
    int i = blockIdx.x * blockDim.x + threadIdx.x;
    if (i < NN * CC) o[i] += b[i & 63];
}

// ---------------- host orchestration ---------------------------------------
extern "C" void kernel_launch(void* const* d_in, const int* in_sizes, int n_in,
                              void* d_out, int out_size)
{
    const float* x   = (const float*)d_in[0];
    const int*   ei  = (const int*)d_in[1];
    const float* W0  = (const float*)d_in[2];
    const float* as0 = (const float*)d_in[3];
    const float* ad0 = (const float*)d_in[4];
    const float* W1  = (const float*)d_in[6];
    const float* as1 = (const float*)d_in[7];
    const float* ad1 = (const float*)d_in[8];
    const float* W2  = (const float*)d_in[10];
    const float* as2 = (const float*)d_in[11];
    const float* ad2 = (const float*)d_in[12];
    const float* b2  = (const float*)d_in[13];
    const float* g0  = (const float*)d_in[14];
    const float* be0 = (const float*)d_in[15];
    const float* g1  = (const float*)d_in[16];
    const float* be1 = (const float*)d_in[17];
    float* out = (float*)d_out;

    float *acc_ptr, *feat_ptr;
    cudaGetSymbolAddress((void**)&acc_ptr, g_acc);
    cudaGetSymbolAddress((void**)&feat_ptr, g_feat);

    const dim3 gemm_block(16, 16);
    const dim3 gemm_grid(4, (NN + 63) / 64);
    const int attn_blocks = (NN * HH * 32 + 255) / 256;
    const int init_blocks = (NN * HH + 255) / 256;
    const int edge_blocks = (ET + 255) / 256;
    const int scat_blocks = (ET * 32 + 255) / 256;
    const int nc_blocks = (NN * CC + 255) / 256;

    // ---- layer 0 ----
    gemm_kernel<256><<<gemm_grid, gemm_block>>>(x, W0, NN);
    attn_kernel<<<attn_blocks, 256>>>(as0, ad0);
    init_kernel<<<init_blocks, 256>>>();
    edge_logit_kernel<<<edge_blocks, 256>>>(ei);
    edge_exp_kernel<<<edge_blocks, 256>>>(ei);
    cudaMemsetAsync(acc_ptr, 0, (size_t)NN * CC * sizeof(float));
    edge_scatter_kernel<<<scat_blocks, 256>>>(ei, acc_ptr);
    bn_stats_kernel<<<512, 256>>>();
    bn_apply_kernel<<<nc_blocks, 256>>>(g0, be0);

    // ---- layer 1 ----
    gemm_kernel<64><<<gemm_grid, gemm_block>>>(feat_ptr, W1, NN);
    attn_kernel<<<attn_blocks, 256>>>(as1, ad1);
    init_kernel<<<init_blocks, 256>>>();
    edge_logit_kernel<<<edge_blocks, 256>>>(ei);
    edge_exp_kernel<<<edge_blocks, 256>>>(ei);
    cudaMemsetAsync(acc_ptr, 0, (size_t)NN * CC * sizeof(float));
    edge_scatter_kernel<<<scat_blocks, 256>>>(ei, acc_ptr);
    bn_stats_kernel<<<512, 256>>>();
    bn_apply_kernel<<<nc_blocks, 256>>>(g1, be1);

    // ---- layer 2 (no BN/ReLU, add bias) ----
    gemm_kernel<64><<<gemm_grid, gemm_block>>>(feat_ptr, W2, NN);
    attn_kernel<<<attn_blocks, 256>>>(as2, ad2);
    init_kernel<<<init_blocks, 256>>>();
    edge_logit_kernel<<<edge_blocks, 256>>>(ei);
    edge_exp_kernel<<<edge_blocks, 256>>>(ei);
    cudaMemsetAsync(out, 0, (size_t)NN * CC * sizeof(float));
    edge_scatter_kernel<<<scat_blocks, 256>>>(ei, out);
    bias_kernel<<<nc_blocks, 256>>>(out, b2);
}

// round 3
// speedup vs baseline: 1.9621x; 1.9621x over previous
#include <cuda_runtime.h>
#include <math.h>

#define NN 50000
#define EE 800000
#define ET (EE + NN)
#define HH 4
#define CC 64
#define HC 256
#define NEG 0.2f
#define EPS_SM 1e-16f
#define EPS_BN 1e-5f
#define FULLM 0xffffffffu
#define NEG_BIG (-1e30f)

// ---------------- scratch ----------------
__device__ float g_h[NN * HC];      // transformed features [N,H,C]
__device__ float g_al[NN * HH];
__device__ float g_ar[NN * HH];
__device__ float g_acc[NN * CC];
__device__ float g_feat[NN * CC];
__device__ float g_bn[2 * CC];      // [0:64) sum, [64:128) sumsq
__device__ int   g_deg[NN];
__device__ int   g_off[NN + 1];
__device__ int   g_cur[NN];
__device__ int   g_srcid[ET];       // CSR (by dst) source node ids

__device__ __forceinline__ float lrelu(float v) { return v > 0.f ? v : NEG * v; }

// ================= CSR build (once per launch) =================
__global__ void deg_init_kernel()
{
    int i = blockIdx.x * blockDim.x + threadIdx.x;
    if (i < NN) g_deg[i] = 1;   // self loop
}

__global__ void hist_kernel(const int* __restrict__ ei)
{
    int e = blockIdx.x * blockDim.x + threadIdx.x;
    if (e < EE) atomicAdd(&g_deg[ei[EE + e]], 1);
}

// single-block exclusive scan over 50k degrees; also seeds self-loop slot
__global__ __launch_bounds__(1024) void scan_kernel()
{
    __shared__ int wsum[32];
    const int T = 1024;
    const int PER = (NN + T - 1) / T;   // 49
    int t = threadIdx.x;
    int base = t * PER;
    int s = 0;
    for (int i = 0; i < PER; i++) {
        int idx = base + i;
        if (idx < NN) s += g_deg[idx];
    }
    int lane = t & 31, w = t >> 5;
    int v = s;
#pragma unroll
    for (int o = 1; o < 32; o <<= 1) {
        int u = __shfl_up_sync(FULLM, v, o);
        if (lane >= o) v += u;
    }
    if (lane == 31) wsum[w] = v;
    __syncthreads();
    if (w == 0) {
        int ws = wsum[lane];
#pragma unroll
        for (int o = 1; o < 32; o <<= 1) {
            int u = __shfl_up_sync(FULLM, ws, o);
            if (lane >= o) ws += u;
        }
        wsum[lane] = ws;
    }
    __syncthreads();
    int run = v - s + (w > 0 ? wsum[w - 1] : 0);
    for (int i = 0; i < PER; i++) {
        int idx = base + i;
        if (idx < NN) {
            g_off[idx] = run;
            g_srcid[run] = idx;      // self loop occupies first slot
            g_cur[idx] = run + 1;
            run += g_deg[idx];
        }
    }
    if (t == T - 1) g_off[NN] = ET;
}

__global__ void scatter_kernel(const int* __restrict__ ei)
{
    int e = blockIdx.x * blockDim.x + threadIdx.x;
    if (e >= EE) return;
    int s = ei[e], d = ei[EE + e];
    int pos = atomicAdd(&g_cur[d], 1);
    g_srcid[pos] = s;
}

// ================= GEMM: C[N,256] = A[N,K] @ B[K,256] =================
// 64x64 tile, BK=16, 128 threads, 8x4 microtile.
template <int K>
__global__ __launch_bounds__(128) void gemm_kernel(
    const float* __restrict__ A, const float* __restrict__ B)
{
    __shared__ float As[16][64];
    __shared__ float Bs[16][64];

    const int row0 = blockIdx.y * 64;
    const int bn0  = blockIdx.x * 64;
    const int tid  = threadIdx.x;
    const int tx   = tid & 15;   // col group (4 cols)
    const int ty   = tid >> 4;   // row group (8 rows)

    float acc[8][4];
#pragma unroll
    for (int i = 0; i < 8; i++)
#pragma unroll
        for (int j = 0; j < 4; j++) acc[i][j] = 0.f;

    for (int k0 = 0; k0 < K; k0 += 16) {
#pragma unroll
        for (int i = 0; i < 8; i++) {
            int r = i * 8 + (tid >> 4);
            int c = tid & 15;
            int gr = row0 + r;
            As[c][r] = (gr < NN) ? A[(size_t)gr * K + k0 + c] : 0.f;
        }
#pragma unroll
        for (int i = 0; i < 8; i++) {
            int idx = i * 128 + tid;
            int kr = idx >> 6, nc = idx & 63;
            Bs[kr][nc] = B[(size_t)(k0 + kr) * 256 + bn0 + nc];
        }
        __syncthreads();

#pragma unroll
        for (int kk = 0; kk < 16; kk++) {
            float4 a0 = *(const float4*)&As[kk][ty * 8];
            float4 a1 = *(const float4*)&As[kk][ty * 8 + 4];
            float4 b0 = *(const float4*)&Bs[kk][tx * 4];
            float av[8] = {a0.x, a0.y, a0.z, a0.w, a1.x, a1.y, a1.z, a1.w};
            float bv[4] = {b0.x, b0.y, b0.z, b0.w};
#pragma unroll
            for (int i = 0; i < 8; i++)
#pragma unroll
                for (int j = 0; j < 4; j++)
                    acc[i][j] = fmaf(av[i], bv[j], acc[i][j]);
        }
        __syncthreads();
    }

#pragma unroll
    for (int i = 0; i < 8; i++) {
        int gr = row0 + ty * 8 + i;
        if (gr < NN) {
            float4 v = make_float4(acc[i][0], acc[i][1], acc[i][2], acc[i][3]);
            *(float4*)&g_h[(size_t)gr * 256 + bn0 + tx * 4] = v;
        }
    }
}

// ================= attention coefficients: warp per (n,h) =================
__global__ __launch_bounds__(256) void attn_kernel(
    const float* __restrict__ asrc, const float* __restrict__ adst)
{
    int widx = (blockIdx.x * blockDim.x + threadIdx.x) >> 5;
    int lane = threadIdx.x & 31;
    if (widx >= NN * HH) return;
    int n = widx >> 2;
    int h = widx & 3;
    const float* hp = g_h + (size_t)n * HC + h * CC;
    float h0 = hp[lane], h1 = hp[lane + 32];
    float sl = h0 * asrc[h * CC + lane] + h1 * asrc[h * CC + lane + 32];
    float sr = h0 * adst[h * CC + lane] + h1 * adst[h * CC + lane + 32];
#pragma unroll
    for (int o = 16; o; o >>= 1) {
        sl += __shfl_down_sync(FULLM, sl, o);
        sr += __shfl_down_sync(FULLM, sr, o);
    }
    if (lane == 0) {
        g_al[widx] = sl;
        g_ar[widx] = sr;
    }
}

// ================= fused softmax + aggregation: warp per dst node ==========
// Online softmax in registers (no atomics), then gather-aggregate with
// warp-broadcast weights. Optional fused BN partial sums / final bias.
// NOTE: running max starts at finite NEG_BIG (not -inf) so that combining two
// empty lanes in the warp reduction gives exp(0)=1 scaled by s=0 (identity),
// never 0*exp(-inf - -inf) = NaN.
template <bool FINAL>
__global__ __launch_bounds__(256) void node_kernel(
    float* __restrict__ out, const float* __restrict__ bias)
{
    __shared__ float sbn[2 * CC];
    if (!FINAL) {
        if (threadIdx.x < 2 * CC) sbn[threadIdx.x] = 0.f;
        __syncthreads();
    }

    const int d    = blockIdx.x * 8 + (threadIdx.x >> 5);   // exactly NN warps
    const int lane = threadIdx.x & 31;
    const int start = g_off[d];
    const int end   = g_off[d + 1];
    const float4 ar = *(const float4*)(g_ar + 4 * d);

    // pass 1: online softmax (max + scaled sum) per head
    float m0 = NEG_BIG, m1 = NEG_BIG, m2 = NEG_BIG, m3 = NEG_BIG;
    float s0 = 0.f, s1 = 0.f, s2 = 0.f, s3 = 0.f;
    for (int sl = start + lane; sl < end; sl += 32) {
        int s = g_srcid[sl];
        float4 al = *(const float4*)(g_al + 4 * s);
        float e0 = lrelu(al.x + ar.x);
        float e1 = lrelu(al.y + ar.y);
        float e2 = lrelu(al.z + ar.z);
        float e3 = lrelu(al.w + ar.w);
        float mn;
        mn = fmaxf(m0, e0); s0 = s0 * __expf(m0 - mn) + __expf(e0 - mn); m0 = mn;
        mn = fmaxf(m1, e1); s1 = s1 * __expf(m1 - mn) + __expf(e1 - mn); m1 = mn;
        mn = fmaxf(m2, e2); s2 = s2 * __expf(m2 - mn) + __expf(e2 - mn); m2 = mn;
        mn = fmaxf(m3, e3); s3 = s3 * __expf(m3 - mn) + __expf(e3 - mn); m3 = mn;
    }
#pragma unroll
    for (int o = 16; o; o >>= 1) {
        float mo, so, mn;
        mo = __shfl_xor_sync(FULLM, m0, o); so = __shfl_xor_sync(FULLM, s0, o);
        mn = fmaxf(m0, mo); s0 = s0 * __expf(m0 - mn) + so * __expf(mo - mn); m0 = mn;
        mo = __shfl_xor_sync(FULLM, m1, o); so = __shfl_xor_sync(FULLM, s1, o);
        mn = fmaxf(m1, mo); s1 = s1 * __expf(m1 - mn) + so * __expf(mo - mn); m1 = mn;
        mo = __shfl_xor_sync(FULLM, m2, o); so = __shfl_xor_sync(FULLM, s2, o);
        mn = fmaxf(m2, mo); s2 = s2 * __expf(m2 - mn) + so * __expf(mo - mn); m2 = mn;
        mo = __shfl_xor_sync(FULLM, m3, o); so = __shfl_xor_sync(FULLM, s3, o);
        mn = fmaxf(m3, mo); s3 = s3 * __expf(m3 - mn) + so * __expf(mo - mn); m3 = mn;
    }
    const float i0 = 0.25f / (s0 + EPS_SM);
    const float i1 = 0.25f / (s1 + EPS_SM);
    const float i2 = 0.25f / (s2 + EPS_SM);
    const float i3 = 0.25f / (s3 + EPS_SM);

    // pass 2: gather-aggregate, 2 channels per lane
    float acc0 = 0.f, acc1 = 0.f;
    for (int base = start; base < end; base += 32) {
        int sl = base + lane;
        int sid = 0;
        float w0 = 0.f, w1 = 0.f, w2 = 0.f, w3 = 0.f;
        if (sl < end) {
            sid = g_srcid[sl];
            float4 al = *(const float4*)(g_al + 4 * sid);
            w0 = __expf(lrelu(al.x + ar.x) - m0) * i0;
            w1 = __expf(lrelu(al.y + ar.y) - m1) * i1;
            w2 = __expf(lrelu(al.z + ar.z) - m2) * i2;
            w3 = __expf(lrelu(al.w + ar.w) - m3) * i3;
        }
        int cnt = min(32, end - base);
        for (int j = 0; j < cnt; j++) {
            int sj = __shfl_sync(FULLM, sid, j);
            float u0 = __shfl_sync(FULLM, w0, j);
            float u1 = __shfl_sync(FULLM, w1, j);
            float u2 = __shfl_sync(FULLM, w2, j);
            float u3 = __shfl_sync(FULLM, w3, j);
            const float* hp = g_h + (size_t)sj * HC;
            acc0 += hp[lane]       * u0 + hp[64 + lane]  * u1
                  + hp[128 + lane] * u2 + hp[192 + lane] * u3;
            acc1 += hp[32 + lane]  * u0 + hp[96 + lane]  * u1
                  + hp[160 + lane] * u2 + hp[224 + lane] * u3;
        }
    }

    if (FINAL) {
        out[(size_t)d * CC + lane]      = acc0 + bias[lane];
        out[(size_t)d * CC + lane + 32] = acc1 + bias[lane + 32];
    } else {
        out[(size_t)d * CC + lane]      = acc0;
        out[(size_t)d * CC + lane + 32] = acc1;
        atomicAdd(&sbn[lane],       acc0);
        atomicAdd(&sbn[32 + lane],  acc1);
        atomicAdd(&sbn[64 + lane],  acc0 * acc0);
        atomicAdd(&sbn[96 + lane],  acc1 * acc1);
        __syncthreads();
        if (threadIdx.x < 2 * CC) atomicAdd(&g_bn[threadIdx.x], sbn[threadIdx.x]);
    }
}

// ================= BN apply + ReLU: g_acc -> g_feat =================
__global__ __launch_bounds__(256) void bn_apply_kernel(
    const float* __restrict__ gam, const float* __restrict__ bet)
{
    int i = blockIdx.x * blockDim.x + threadIdx.x;
    if (i >= NN * CC) return;
    int c = i & 63;
    const float inv_n = 1.f / (float)NN;
    float mu = g_bn[c] * inv_n;
    float var = g_bn[64 + c] * inv_n - mu * mu;
    float y = (g_acc[i] - mu) * rsqrtf(var + EPS_BN) * gam[c] + bet[c];
    g_feat[i] = fmaxf(y, 0.f);
}

// ================= host orchestration =================
extern "C" void kernel_launch(void* const* d_in, const int* in_sizes, int n_in,
                              void* d_out, int out_size)
{
    const float* x   = (const float*)d_in[0];
    const int*   ei  = (const int*)d_in[1];
    const float* W0  = (const float*)d_in[2];
    const float* as0 = (const float*)d_in[3];
    const float* ad0 = (const float*)d_in[4];
    const float* W1  = (const float*)d_in[6];
    const float* as1 = (const float*)d_in[7];
    const float* ad1 = (const float*)d_in[8];
    const float* W2  = (const float*)d_in[10];
    const float* as2 = (const float*)d_in[11];
    const float* ad2 = (const float*)d_in[12];
    const float* b2  = (const float*)d_in[13];
    const float* g0  = (const float*)d_in[14];
    const float* be0 = (const float*)d_in[15];
    const float* g1  = (const float*)d_in[16];
    const float* be1 = (const float*)d_in[17];
    float* out = (float*)d_out;

    float *acc_ptr, *feat_ptr, *bn_ptr;
    cudaGetSymbolAddress((void**)&acc_ptr, g_acc);
    cudaGetSymbolAddress((void**)&feat_ptr, g_feat);
    cudaGetSymbolAddress((void**)&bn_ptr, g_bn);

    const dim3 gemm_block(128);
    const dim3 gemm_grid(4, (NN + 63) / 64);
    const int attn_blocks = (NN * HH * 32 + 255) / 256;
    const int node_blocks = NN / 8;          // 6250, warp per node
    const int nc_blocks   = (NN * CC + 255) / 256;
    const int edge_blocks = (EE + 255) / 256;

    // ---- CSR build (edge structure is layer-invariant) ----
    deg_init_kernel<<<(NN + 255) / 256, 256>>>();
    hist_kernel<<<edge_blocks, 256>>>(ei);
    scan_kernel<<<1, 1024>>>();
    scatter_kernel<<<edge_blocks, 256>>>(ei);

    // ---- layer 0 ----
    gemm_kernel<256><<<gemm_grid, gemm_block>>>(x, W0);
    attn_kernel<<<attn_blocks, 256>>>(as0, ad0);
    cudaMemsetAsync(bn_ptr, 0, 2 * CC * sizeof(float));
    node_kernel<false><<<node_blocks, 256>>>(acc_ptr, nullptr);
    bn_apply_kernel<<<nc_blocks, 256>>>(g0, be0);

    // ---- layer 1 ----
    gemm_kernel<64><<<gemm_grid, gemm_block>>>(feat_ptr, W1);
    attn_kernel<<<attn_blocks, 256>>>(as1, ad1);
    cudaMemsetAsync(bn_ptr, 0, 2 * CC * sizeof(float));
    node_kernel<false><<<node_blocks, 256>>>(acc_ptr, nullptr);
    bn_apply_kernel<<<nc_blocks, 256>>>(g1, be1);

    // ---- layer 2 ----
    gemm_kernel<64><<<gemm_grid, gemm_block>>>(feat_ptr, W2);
    attn_kernel<<<attn_blocks, 256>>>(as2, ad2);
    node_kernel<true><<<node_blocks, 256>>>(out, b2);
}

// round 7
// speedup vs baseline: 2.3054x; 1.1749x over previous
#include <cuda_runtime.h>
#include <cuda_fp16.h>
#include <math.h>

#define NN 50000
#define EE 800000
#define ET (EE + NN)
#define HH 4
#define CC 64
#define HC 256
#define NEG 0.2f
#define EPS_SM 1e-16f
#define EPS_BN 1e-5f
#define FULLM 0xffffffffu
#define NEG_BIG (-1e30f)

// ---------------- scratch ----------------
__device__ float g_h[NN * HC];      // transformed features [N,H,C]
__device__ float g_al[NN * HH];
__device__ float g_ar[NN * HH];
__device__ float g_acc[NN * CC];
__device__ float g_feat[NN * CC];
__device__ float g_bn[2 * CC];      // [0:64) sum, [64:128) sumsq
__device__ int   g_deg[NN];
__device__ int   g_off[NN + 1];
__device__ int   g_cur[NN];
__device__ int   g_srcid[ET];       // CSR (by dst) source node ids

__device__ __forceinline__ float lrelu(float v) { return v > 0.f ? v : NEG * v; }

__device__ __forceinline__ unsigned sptr(const void* p) {
    return (unsigned)__cvta_generic_to_shared(p);
}

// ================= CSR build (once per launch) =================
__global__ void deg_init_kernel()
{
    int i = blockIdx.x * blockDim.x + threadIdx.x;
    if (i < NN) g_deg[i] = 1;   // self loop
}

__global__ void hist_kernel(const int* __restrict__ ei)
{
    int e = blockIdx.x * blockDim.x + threadIdx.x;
    if (e < EE) atomicAdd(&g_deg[ei[EE + e]], 1);
}

__global__ __launch_bounds__(1024) void scan_kernel()
{
    __shared__ int wsum[32];
    const int T = 1024;
    const int PER = (NN + T - 1) / T;
    int t = threadIdx.x;
    int base = t * PER;
    int s = 0;
    for (int i = 0; i < PER; i++) {
        int idx = base + i;
        if (idx < NN) s += g_deg[idx];
    }
    int lane = t & 31, w = t >> 5;
    int v = s;
#pragma unroll
    for (int o = 1; o < 32; o <<= 1) {
        int u = __shfl_up_sync(FULLM, v, o);
        if (lane >= o) v += u;
    }
    if (lane == 31) wsum[w] = v;
    __syncthreads();
    if (w == 0) {
        int ws = wsum[lane];
#pragma unroll
        for (int o = 1; o < 32; o <<= 1) {
            int u = __shfl_up_sync(FULLM, ws, o);
            if (lane >= o) ws += u;
        }
        wsum[lane] = ws;
    }
    __syncthreads();
    int run = v - s + (w > 0 ? wsum[w - 1] : 0);
    for (int i = 0; i < PER; i++) {
        int idx = base + i;
        if (idx < NN) {
            g_off[idx] = run;
            g_srcid[run] = idx;      // self loop occupies first slot
            g_cur[idx] = run + 1;
            run += g_deg[idx];
        }
    }
    if (t == T - 1) g_off[NN] = ET;
}

__global__ void scatter_kernel(const int* __restrict__ ei)
{
    int e = blockIdx.x * blockDim.x + threadIdx.x;
    if (e >= EE) return;
    int s = ei[e], d = ei[EE + e];
    int pos = atomicAdd(&g_cur[d], 1);
    g_srcid[pos] = s;
}

// ================= tensor-core GEMM =================
// C[N,256] = A[N,K] @ B[K,256] via mma.sync m16n8k16 fp16, 3-term hi/lo split
// (error ~2^-22, effectively fp32). Block tile 128x64, BK=32, 8 warps (4m x 2n),
// warp tile 32x32 = 2x4 mma tiles.
#define ASTR 40   // As row stride in halves (80B): conflict-free ldmatrix
#define BSTR 72   // Bs row stride in halves (144B): conflict-free ldmatrix.trans

__device__ __forceinline__ void mma16816(float* c, const unsigned* a, const unsigned* b)
{
    asm volatile(
        "mma.sync.aligned.m16n8k16.row.col.f32.f16.f16.f32 "
        "{%0,%1,%2,%3}, {%4,%5,%6,%7}, {%8,%9}, {%0,%1,%2,%3};"
        : "+f"(c[0]), "+f"(c[1]), "+f"(c[2]), "+f"(c[3])
        : "r"(a[0]), "r"(a[1]), "r"(a[2]), "r"(a[3]), "r"(b[0]), "r"(b[1]));
}

__device__ __forceinline__ void ldm_x4(unsigned* r, unsigned addr)
{
    asm volatile("ldmatrix.sync.aligned.m8n8.x4.shared.b16 {%0,%1,%2,%3}, [%4];"
                 : "=r"(r[0]), "=r"(r[1]), "=r"(r[2]), "=r"(r[3]) : "r"(addr));
}

__device__ __forceinline__ void ldm_x2t(unsigned* r, unsigned addr)
{
    asm volatile("ldmatrix.sync.aligned.m8n8.x2.trans.shared.b16 {%0,%1}, [%2];"
                 : "=r"(r[0]), "=r"(r[1]) : "r"(addr));
}

template <int K>
__global__ __launch_bounds__(256, 2) void mma_gemm_kernel(
    const float* __restrict__ A, const float* __restrict__ B)
{
    __shared__ __half As_hi[128][ASTR];
    __shared__ __half As_lo[128][ASTR];
    __shared__ __half Bs_hi[32][BSTR];
    __shared__ __half Bs_lo[32][BSTR];

    const int row0 = blockIdx.y * 128;
    const int bn0  = blockIdx.x * 64;
    const int tid  = threadIdx.x;
    const int lane = tid & 31;
    const int wid  = tid >> 5;
    const int warp_m = wid & 3;      // 0..3 -> m offset *32
    const int warp_n = wid >> 2;     // 0..1 -> n offset *32
    const int g  = lane >> 2;
    const int tq = lane & 3;

    float acc[2][4][4];
#pragma unroll
    for (int mi = 0; mi < 2; mi++)
#pragma unroll
        for (int ni = 0; ni < 4; ni++)
#pragma unroll
            for (int q = 0; q < 4; q++) acc[mi][ni][q] = 0.f;

    // global-load assignments
    const int ar  = tid >> 1;            // A row 0..127
    const int ac0 = (tid & 1) * 16;      // A col base
    const int br  = tid >> 3;            // B row 0..31
    const int bc0 = (tid & 7) * 8;       // B col base

    for (int k0 = 0; k0 < K; k0 += 32) {
        // ---- load + split A tile [128 x 32] ----
        {
            int gr = row0 + ar;
            bool ok = gr < NN;
            const float* ap = A + (size_t)gr * K + k0 + ac0;
#pragma unroll
            for (int v = 0; v < 4; v++) {
                float4 f = ok ? *(const float4*)(ap + v * 4)
                              : make_float4(0.f, 0.f, 0.f, 0.f);
                float fv[4] = {f.x, f.y, f.z, f.w};
#pragma unroll
                for (int i = 0; i < 4; i++) {
                    int c = ac0 + v * 4 + i;
                    __half hi = __float2half_rn(fv[i]);
                    __half lo = __float2half_rn(fv[i] - __half2float(hi));
                    As_hi[ar][c] = hi;
                    As_lo[ar][c] = lo;
                }
            }
        }
        // ---- load + split B tile [32 x 64] ----
        {
            const float* bp = B + (size_t)(k0 + br) * 256 + bn0 + bc0;
#pragma unroll
            for (int v = 0; v < 2; v++) {
                float4 f = *(const float4*)(bp + v * 4);
                float fv[4] = {f.x, f.y, f.z, f.w};
#pragma unroll
                for (int i = 0; i < 4; i++) {
                    int c = bc0 + v * 4 + i;
                    __half hi = __float2half_rn(fv[i]);
                    __half lo = __float2half_rn(fv[i] - __half2float(hi));
                    Bs_hi[br][c] = hi;
                    Bs_lo[br][c] = lo;
                }
            }
        }
        __syncthreads();

#pragma unroll
        for (int ks = 0; ks < 2; ks++) {
            unsigned ahi[2][4], alo[2][4], bhi[4][2], blo[4][2];
#pragma unroll
            for (int mi = 0; mi < 2; mi++) {
                int r = warp_m * 32 + mi * 16 + (lane & 15);
                int c = ks * 16 + (lane >> 4) * 8;
                ldm_x4(ahi[mi], sptr(&As_hi[r][c]));
                ldm_x4(alo[mi], sptr(&As_lo[r][c]));
            }
#pragma unroll
            for (int ni = 0; ni < 4; ni++) {
                int r = ks * 16 + (lane & 15);
                int c = warp_n * 32 + ni * 8;
                ldm_x2t(bhi[ni], sptr(&Bs_hi[r][c]));
                ldm_x2t(blo[ni], sptr(&Bs_lo[r][c]));
            }
#pragma unroll
            for (int mi = 0; mi < 2; mi++)
#pragma unroll
                for (int ni = 0; ni < 4; ni++) {
                    mma16816(acc[mi][ni], ahi[mi], bhi[ni]);
                    mma16816(acc[mi][ni], ahi[mi], blo[ni]);
                    mma16816(acc[mi][ni], alo[mi], bhi[ni]);
                }
        }
        __syncthreads();
    }

    // ---- epilogue: write fp32 g_h ----
#pragma unroll
    for (int mi = 0; mi < 2; mi++) {
        int r = row0 + warp_m * 32 + mi * 16 + g;
#pragma unroll
        for (int ni = 0; ni < 4; ni++) {
            int c = bn0 + warp_n * 32 + ni * 8 + 2 * tq;
            if (r < NN)
                *(float2*)&g_h[(size_t)r * 256 + c] =
                    make_float2(acc[mi][ni][0], acc[mi][ni][1]);
            if (r + 8 < NN)
                *(float2*)&g_h[(size_t)(r + 8) * 256 + c] =
                    make_float2(acc[mi][ni][2], acc[mi][ni][3]);
        }
    }
}

// ================= attention coefficients: warp per (n,h) =================
__global__ __launch_bounds__(256) void attn_kernel(
    const float* __restrict__ asrc, const float* __restrict__ adst)
{
    int widx = (blockIdx.x * blockDim.x + threadIdx.x) >> 5;
    int lane = threadIdx.x & 31;
    if (widx >= NN * HH) return;
    int n = widx >> 2;
    int h = widx & 3;
    const float* hp = g_h + (size_t)n * HC + h * CC;
    float h0 = hp[lane], h1 = hp[lane + 32];
    float sl = h0 * asrc[h * CC + lane] + h1 * asrc[h * CC + lane + 32];
    float sr = h0 * adst[h * CC + lane] + h1 * adst[h * CC + lane + 32];
#pragma unroll
    for (int o = 16; o; o >>= 1) {
        sl += __shfl_down_sync(FULLM, sl, o);
        sr += __shfl_down_sync(FULLM, sr, o);
    }
    if (lane == 0) {
        g_al[widx] = sl;
        g_ar[widx] = sr;
    }
}

// ================= fused softmax + aggregation: warp per dst node ==========
template <bool FINAL>
__global__ __launch_bounds__(256) void node_kernel(
    float* __restrict__ out, const float* __restrict__ bias)
{
    __shared__ float sbn[2 * CC];
    if (!FINAL) {
        if (threadIdx.x < 2 * CC) sbn[threadIdx.x] = 0.f;
        __syncthreads();
    }

    const int d    = blockIdx.x * 8 + (threadIdx.x >> 5);
    const int lane = threadIdx.x & 31;
    const int start = g_off[d];
    const int end   = g_off[d + 1];
    const float4 ar = *(const float4*)(g_ar + 4 * d);

    // pass 1: online softmax per head (finite sentinel avoids NaN on empty lanes)
    float m0 = NEG_BIG, m1 = NEG_BIG, m2 = NEG_BIG, m3 = NEG_BIG;
    float s0 = 0.f, s1 = 0.f, s2 = 0.f, s3 = 0.f;
    for (int sl = start + lane; sl < end; sl += 32) {
        int s = g_srcid[sl];
        float4 al = *(const float4*)(g_al + 4 * s);
        float e0 = lrelu(al.x + ar.x);
        float e1 = lrelu(al.y + ar.y);
        float e2 = lrelu(al.z + ar.z);
        float e3 = lrelu(al.w + ar.w);
        float mn;
        mn = fmaxf(m0, e0); s0 = s0 * __expf(m0 - mn) + __expf(e0 - mn); m0 = mn;
        mn = fmaxf(m1, e1); s1 = s1 * __expf(m1 - mn) + __expf(e1 - mn); m1 = mn;
        mn = fmaxf(m2, e2); s2 = s2 * __expf(m2 - mn) + __expf(e2 - mn); m2 = mn;
        mn = fmaxf(m3, e3); s3 = s3 * __expf(m3 - mn) + __expf(e3 - mn); m3 = mn;
    }
#pragma unroll
    for (int o = 16; o; o >>= 1) {
        float mo, so, mn;
        mo = __shfl_xor_sync(FULLM, m0, o); so = __shfl_xor_sync(FULLM, s0, o);
        mn = fmaxf(m0, mo); s0 = s0 * __expf(m0 - mn) + so * __expf(mo - mn); m0 = mn;
        mo = __shfl_xor_sync(FULLM, m1, o); so = __shfl_xor_sync(FULLM, s1, o);
        mn = fmaxf(m1, mo); s1 = s1 * __expf(m1 - mn) + so * __expf(mo - mn); m1 = mn;
        mo = __shfl_xor_sync(FULLM, m2, o); so = __shfl_xor_sync(FULLM, s2, o);
        mn = fmaxf(m2, mo); s2 = s2 * __expf(m2 - mn) + so * __expf(mo - mn); m2 = mn;
        mo = __shfl_xor_sync(FULLM, m3, o); so = __shfl_xor_sync(FULLM, s3, o);
        mn = fmaxf(m3, mo); s3 = s3 * __expf(m3 - mn) + so * __expf(mo - mn); m3 = mn;
    }
    const float i0 = 0.25f / (s0 + EPS_SM);
    const float i1 = 0.25f / (s1 + EPS_SM);
    const float i2 = 0.25f / (s2 + EPS_SM);
    const float i3 = 0.25f / (s3 + EPS_SM);

    // pass 2: gather-aggregate, 2 channels per lane
    float acc0 = 0.f, acc1 = 0.f;
    for (int base = start; base < end; base += 32) {
        int sl = base + lane;
        int sid = 0;
        float w0 = 0.f, w1 = 0.f, w2 = 0.f, w3 = 0.f;
        if (sl < end) {
            sid = g_srcid[sl];
            float4 al = *(const float4*)(g_al + 4 * sid);
            w0 = __expf(lrelu(al.x + ar.x) - m0) * i0;
            w1 = __expf(lrelu(al.y + ar.y) - m1) * i1;
            w2 = __expf(lrelu(al.z + ar.z) - m2) * i2;
            w3 = __expf(lrelu(al.w + ar.w) - m3) * i3;
        }
        int cnt = min(32, end - base);
        for (int j = 0; j < cnt; j++) {
            int sj = __shfl_sync(FULLM, sid, j);
            float u0 = __shfl_sync(FULLM, w0, j);
            float u1 = __shfl_sync(FULLM, w1, j);
            float u2 = __shfl_sync(FULLM, w2, j);
            float u3 = __shfl_sync(FULLM, w3, j);
            const float* hp = g_h + (size_t)sj * HC;
            acc0 += hp[lane]       * u0 + hp[64 + lane]  * u1
                  + hp[128 + lane] * u2 + hp[192 + lane] * u3;
            acc1 += hp[32 + lane]  * u0 + hp[96 + lane]  * u1
                  + hp[160 + lane] * u2 + hp[224 + lane] * u3;
        }
    }

    if (FINAL) {
        out[(size_t)d * CC + lane]      = acc0 + bias[lane];
        out[(size_t)d * CC + lane + 32] = acc1 + bias[lane + 32];
    } else {
        out[(size_t)d * CC + lane]      = acc0;
        out[(size_t)d * CC + lane + 32] = acc1;
        atomicAdd(&sbn[lane],       acc0);
        atomicAdd(&sbn[32 + lane],  acc1);
        atomicAdd(&sbn[64 + lane],  acc0 * acc0);
        atomicAdd(&sbn[96 + lane],  acc1 * acc1);
        __syncthreads();
        if (threadIdx.x < 2 * CC) atomicAdd(&g_bn[threadIdx.x], sbn[threadIdx.x]);
    }
}

// ================= BN apply + ReLU: g_acc -> g_feat =================
__global__ __launch_bounds__(256) void bn_apply_kernel(
    const float* __restrict__ gam, const float* __restrict__ bet)
{
    int i = blockIdx.x * blockDim.x + threadIdx.x;
    if (i >= NN * CC) return;
    int c = i & 63;
    const float inv_n = 1.f / (float)NN;
    float mu = g_bn[c] * inv_n;
    float var = g_bn[64 + c] * inv_n - mu * mu;
    float y = (g_acc[i] - mu) * rsqrtf(var + EPS_BN) * gam[c] + bet[c];
    g_feat[i] = fmaxf(y, 0.f);
}

// ================= host orchestration =================
extern "C" void kernel_launch(void* const* d_in, const int* in_sizes, int n_in,
                              void* d_out, int out_size)
{
    const float* x   = (const float*)d_in[0];
    const int*   ei  = (const int*)d_in[1];
    const float* W0  = (const float*)d_in[2];
    const float* as0 = (const float*)d_in[3];
    const float* ad0 = (const float*)d_in[4];
    const float* W1  = (const float*)d_in[6];
    const float* as1 = (const float*)d_in[7];
    const float* ad1 = (const float*)d_in[8];
    const float* W2  = (const float*)d_in[10];
    const float* as2 = (const float*)d_in[11];
    const float* ad2 = (const float*)d_in[12];
    const float* b2  = (const float*)d_in[13];
    const float* g0  = (const float*)d_in[14];
    const float* be0 = (const float*)d_in[15];
    const float* g1  = (const float*)d_in[16];
    const float* be1 = (const float*)d_in[17];
    float* out = (float*)d_out;

    float *acc_ptr, *feat_ptr, *bn_ptr;
    cudaGetSymbolAddress((void**)&acc_ptr, g_acc);
    cudaGetSymbolAddress((void**)&feat_ptr, g_feat);
    cudaGetSymbolAddress((void**)&bn_ptr, g_bn);

    const dim3 gemm_grid(4, (NN + 127) / 128);   // 4 x 391
    const int attn_blocks = (NN * HH * 32 + 255) / 256;
    const int node_blocks = NN / 8;
    const int nc_blocks   = (NN * CC + 255) / 256;
    const int edge_blocks = (EE + 255) / 256;

    // ---- CSR build (edge structure is layer-invariant) ----
    deg_init_kernel<<<(NN + 255) / 256, 256>>>();
    hist_kernel<<<edge_blocks, 256>>>(ei);
    scan_kernel<<<1, 1024>>>();
    scatter_kernel<<<edge_blocks, 256>>>(ei);

    // ---- layer 0 ----
    mma_gemm_kernel<256><<<gemm_grid, 256>>>(x, W0);
    attn_kernel<<<attn_blocks, 256>>>(as0, ad0);
    cudaMemsetAsync(bn_ptr, 0, 2 * CC * sizeof(float));
    node_kernel<false><<<node_blocks, 256>>>(acc_ptr, nullptr);
    bn_apply_kernel<<<nc_blocks, 256>>>(g0, be0);

    // ---- layer 1 ----
    mma_gemm_kernel<64><<<gemm_grid, 256>>>(feat_ptr, W1);
    attn_kernel<<<attn_blocks, 256>>>(as1, ad1);
    cudaMemsetAsync(bn_ptr, 0, 2 * CC * sizeof(float));
    node_kernel<false><<<node_blocks, 256>>>(acc_ptr, nullptr);
    bn_apply_kernel<<<nc_blocks, 256>>>(g1, be1);

    // ---- layer 2 ----
    mma_gemm_kernel<64><<<gemm_grid, 256>>>(feat_ptr, W2);
    attn_kernel<<<attn_blocks, 256>>>(as2, ad2);
    node_kernel<true><<<node_blocks, 256>>>(out, b2);
}

// round 9
// speedup vs baseline: 2.5280x; 1.0966x over previous
#include <cuda_runtime.h>
#include <cuda_fp16.h>
#include <math.h>

#define NN 50000
#define EE 800000
#define ET (EE + NN)
#define HH 4
#define CC 64
#define HC 256
#define NEG 0.2f
#define EPS_SM 1e-16f
#define EPS_BN 1e-5f
#define FULLM 0xffffffffu
#define NEG_BIG (-1e30f)

// ---------------- scratch ----------------
__device__ float g_h[NN * HC];      // transformed features [N,H,C]
__device__ float g_al[NN * HH];     // attn src terms (atomic-accumulated by GEMM)
__device__ float g_ar[NN * HH];
__device__ float g_acc[NN * CC];    // aggregation output / next-layer input
__device__ float g_bn[2 * CC];      // [0:64) sum, [64:128) sumsq
__device__ float g_scale[CC];       // BN folded scale
__device__ float g_shift[CC];       // BN folded shift
__device__ int   g_deg[NN];
__device__ int   g_off[NN + 1];
__device__ int   g_cur[NN];
__device__ int   g_srcid[ET];       // CSR (by dst) source node ids

__device__ __forceinline__ float lrelu(float v) { return v > 0.f ? v : NEG * v; }

__device__ __forceinline__ unsigned sptr(const void* p) {
    return (unsigned)__cvta_generic_to_shared(p);
}

// ================= CSR build (once per launch) =================
__global__ void hist_kernel(const int* __restrict__ ei)
{
    int e = blockIdx.x * blockDim.x + threadIdx.x;
    if (e < EE) atomicAdd(&g_deg[ei[EE + e]], 1);
}

// single-block exclusive scan; self-loop (+1 degree) folded in here
__global__ __launch_bounds__(1024) void scan_kernel()
{
    __shared__ int wsum[32];
    const int T = 1024;
    const int PER = (NN + T - 1) / T;
    int t = threadIdx.x;
    int base = t * PER;
    int s = 0;
    for (int i = 0; i < PER; i++) {
        int idx = base + i;
        if (idx < NN) s += g_deg[idx] + 1;
    }
    int lane = t & 31, w = t >> 5;
    int v = s;
#pragma unroll
    for (int o = 1; o < 32; o <<= 1) {
        int u = __shfl_up_sync(FULLM, v, o);
        if (lane >= o) v += u;
    }
    if (lane == 31) wsum[w] = v;
    __syncthreads();
    if (w == 0) {
        int ws = wsum[lane];
#pragma unroll
        for (int o = 1; o < 32; o <<= 1) {
            int u = __shfl_up_sync(FULLM, ws, o);
            if (lane >= o) ws += u;
        }
        wsum[lane] = ws;
    }
    __syncthreads();
    int run = v - s + (w > 0 ? wsum[w - 1] : 0);
    for (int i = 0; i < PER; i++) {
        int idx = base + i;
        if (idx < NN) {
            int dg = g_deg[idx] + 1;
            g_off[idx] = run;
            g_srcid[run] = idx;      // self loop occupies first slot
            g_cur[idx] = run + 1;
            run += dg;
        }
    }
    if (t == T - 1) g_off[NN] = ET;
}

__global__ void scatter_kernel(const int* __restrict__ ei)
{
    int e = blockIdx.x * blockDim.x + threadIdx.x;
    if (e >= EE) return;
    int s = ei[e], d = ei[EE + e];
    int pos = atomicAdd(&g_cur[d], 1);
    g_srcid[pos] = s;
}

// ================= tensor-core GEMM + fused BN(A) + fused attn epilogue ====
// C[N,256] = A[N,K] @ B[K,256], mma m16n8k16 fp16 3-term hi/lo split.
// Block tile 128x64, BK=32, 8 warps (4m x 2n). blockIdx.x == head index,
// so the epilogue computes complete al/ar dot products for this head
// (2 atomicAdd contributors per (row,head): order-independent fp add).
#define ASTR 40
#define BSTR 72

__device__ __forceinline__ void mma16816(float* c, const unsigned* a, const unsigned* b)
{
    asm volatile(
        "mma.sync.aligned.m16n8k16.row.col.f32.f16.f16.f32 "
        "{%0,%1,%2,%3}, {%4,%5,%6,%7}, {%8,%9}, {%0,%1,%2,%3};"
        : "+f"(c[0]), "+f"(c[1]), "+f"(c[2]), "+f"(c[3])
        : "r"(a[0]), "r"(a[1]), "r"(a[2]), "r"(a[3]), "r"(b[0]), "r"(b[1]));
}

__device__ __forceinline__ void ldm_x4(unsigned* r, unsigned addr)
{
    asm volatile("ldmatrix.sync.aligned.m8n8.x4.shared.b16 {%0,%1,%2,%3}, [%4];"
                 : "=r"(r[0]), "=r"(r[1]), "=r"(r[2]), "=r"(r[3]) : "r"(addr));
}

__device__ __forceinline__ void ldm_x2t(unsigned* r, unsigned addr)
{
    asm volatile("ldmatrix.sync.aligned.m8n8.x2.trans.shared.b16 {%0,%1}, [%2];"
                 : "=r"(r[0]), "=r"(r[1]) : "r"(addr));
}

template <int K, bool BN>
__global__ __launch_bounds__(256, 2) void mma_gemm_kernel(
    const float* __restrict__ A, const float* __restrict__ B,
    const float* __restrict__ asrc, const float* __restrict__ adst)
{
    __shared__ __half As_hi[128][ASTR];
    __shared__ __half As_lo[128][ASTR];
    __shared__ __half Bs_hi[32][BSTR];
    __shared__ __half Bs_lo[32][BSTR];

    const int row0 = blockIdx.y * 128;
    const int bn0  = blockIdx.x * 64;
    const int tid  = threadIdx.x;
    const int lane = tid & 31;
    const int wid  = tid >> 5;
    const int warp_m = wid & 3;
    const int warp_n = wid >> 2;
    const int g  = lane >> 2;
    const int tq = lane & 3;

    float acc[2][4][4];
#pragma unroll
    for (int mi = 0; mi < 2; mi++)
#pragma unroll
        for (int ni = 0; ni < 4; ni++)
#pragma unroll
            for (int q = 0; q < 4; q++) acc[mi][ni][q] = 0.f;

    const int ar  = tid >> 1;
    const int ac0 = (tid & 1) * 16;
    const int br  = tid >> 3;
    const int bc0 = (tid & 7) * 8;

    for (int k0 = 0; k0 < K; k0 += 32) {
        // ---- load (+BN+ReLU) + split A tile [128 x 32] ----
        {
            int gr = row0 + ar;
            bool ok = gr < NN;
            const float* ap = A + (size_t)gr * K + k0 + ac0;
#pragma unroll
            for (int v = 0; v < 4; v++) {
                float4 f = ok ? *(const float4*)(ap + v * 4)
                              : make_float4(0.f, 0.f, 0.f, 0.f);
                float fv[4] = {f.x, f.y, f.z, f.w};
#pragma unroll
                for (int i = 0; i < 4; i++) {
                    int c = ac0 + v * 4 + i;
                    float val = fv[i];
                    if (BN && ok)
                        val = fmaxf(fmaf(val, g_scale[k0 + c], g_shift[k0 + c]), 0.f);
                    __half hi = __float2half_rn(val);
                    __half lo = __float2half_rn(val - __half2float(hi));
                    As_hi[ar][c] = hi;
                    As_lo[ar][c] = lo;
                }
            }
        }
        // ---- load + split B tile [32 x 64] ----
        {
            const float* bp = B + (size_t)(k0 + br) * 256 + bn0 + bc0;
#pragma unroll
            for (int v = 0; v < 2; v++) {
                float4 f = *(const float4*)(bp + v * 4);
                float fv[4] = {f.x, f.y, f.z, f.w};
#pragma unroll
                for (int i = 0; i < 4; i++) {
                    int c = bc0 + v * 4 + i;
                    __half hi = __float2half_rn(fv[i]);
                    __half lo = __float2half_rn(fv[i] - __half2float(hi));
                    Bs_hi[br][c] = hi;
                    Bs_lo[br][c] = lo;
                }
            }
        }
        __syncthreads();

#pragma unroll
        for (int ks = 0; ks < 2; ks++) {
            unsigned ahi[2][4], alo[2][4], bhi[4][2], blo[4][2];
#pragma unroll
            for (int mi = 0; mi < 2; mi++) {
                int r = warp_m * 32 + mi * 16 + (lane & 15);
                int c = ks * 16 + (lane >> 4) * 8;
                ldm_x4(ahi[mi], sptr(&As_hi[r][c]));
                ldm_x4(alo[mi], sptr(&As_lo[r][c]));
            }
#pragma unroll
            for (int ni = 0; ni < 4; ni++) {
                int r = ks * 16 + (lane & 15);
                int c = warp_n * 32 + ni * 8;
                ldm_x2t(bhi[ni], sptr(&Bs_hi[r][c]));
                ldm_x2t(blo[ni], sptr(&Bs_lo[r][c]));
            }
#pragma unroll
            for (int mi = 0; mi < 2; mi++)
#pragma unroll
                for (int ni = 0; ni < 4; ni++) {
                    mma16816(acc[mi][ni], ahi[mi], bhi[ni]);
                    mma16816(acc[mi][ni], ahi[mi], blo[ni]);
                    mma16816(acc[mi][ni], alo[mi], bhi[ni]);
                }
        }
        __syncthreads();
    }

    // ---- epilogue 1: write fp32 g_h ----
#pragma unroll
    for (int mi = 0; mi < 2; mi++) {
        int r = row0 + warp_m * 32 + mi * 16 + g;
#pragma unroll
        for (int ni = 0; ni < 4; ni++) {
            int c = bn0 + warp_n * 32 + ni * 8 + 2 * tq;
            if (r < NN)
                *(float2*)&g_h[(size_t)r * 256 + c] =
                    make_float2(acc[mi][ni][0], acc[mi][ni][1]);
            if (r + 8 < NN)
                *(float2*)&g_h[(size_t)(r + 8) * 256 + c] =
                    make_float2(acc[mi][ni][2], acc[mi][ni][3]);
        }
    }

    // ---- epilogue 2: fused attention coefficients for head = blockIdx.x ----
    {
        const int h = blockIdx.x;
        const float* asb = asrc + h * CC;
        const float* adb = adst + h * CC;
        float sl[2][2] = {{0.f, 0.f}, {0.f, 0.f}};
        float sr[2][2] = {{0.f, 0.f}, {0.f, 0.f}};
#pragma unroll
        for (int mi = 0; mi < 2; mi++)
#pragma unroll
            for (int ni = 0; ni < 4; ni++)
#pragma unroll
                for (int q = 0; q < 4; q++) {
                    int cl = warp_n * 32 + ni * 8 + 2 * tq + (q & 1);
                    float v = acc[mi][ni][q];
                    sl[mi][q >> 1] = fmaf(v, asb[cl], sl[mi][q >> 1]);
                    sr[mi][q >> 1] = fmaf(v, adb[cl], sr[mi][q >> 1]);
                }
#pragma unroll
        for (int mi = 0; mi < 2; mi++)
#pragma unroll
            for (int hf = 0; hf < 2; hf++) {
                float a = sl[mi][hf], b = sr[mi][hf];
                a += __shfl_xor_sync(FULLM, a, 1);
                a += __shfl_xor_sync(FULLM, a, 2);
                b += __shfl_xor_sync(FULLM, b, 1);
                b += __shfl_xor_sync(FULLM, b, 2);
                int r = row0 + warp_m * 32 + mi * 16 + g + hf * 8;
                if (tq == 0 && r < NN) {
                    atomicAdd(&g_al[r * 4 + h], a);
                    atomicAdd(&g_ar[r * 4 + h], b);
                }
            }
    }
}

// ================= fused softmax + aggregation: warp per dst node ==========
template <bool FINAL>
__global__ __launch_bounds__(256) void node_kernel(
    float* __restrict__ out, const float* __restrict__ bias)
{
    __shared__ float sbn[2 * CC];
    if (!FINAL) {
        if (threadIdx.x < 2 * CC) sbn[threadIdx.x] = 0.f;
        __syncthreads();
    }

    const int d    = blockIdx.x * 8 + (threadIdx.x >> 5);
    const int lane = threadIdx.x & 31;
    const int start = g_off[d];
    const int end   = g_off[d + 1];
    const float4 ar = *(const float4*)(g_ar + 4 * d);

    // pass 1: online softmax per head (finite sentinel avoids NaN on empty lanes)
    float m0 = NEG_BIG, m1 = NEG_BIG, m2 = NEG_BIG, m3 = NEG_BIG;
    float s0 = 0.f, s1 = 0.f, s2 = 0.f, s3 = 0.f;
    for (int sl = start + lane; sl < end; sl += 32) {
        int s = g_srcid[sl];
        float4 al = *(const float4*)(g_al + 4 * s);
        float e0 = lrelu(al.x + ar.x);
        float e1 = lrelu(al.y + ar.y);
        float e2 = lrelu(al.z + ar.z);
        float e3 = lrelu(al.w + ar.w);
        float mn;
        mn = fmaxf(m0, e0); s0 = s0 * __expf(m0 - mn) + __expf(e0 - mn); m0 = mn;
        mn = fmaxf(m1, e1); s1 = s1 * __expf(m1 - mn) + __expf(e1 - mn); m1 = mn;
        mn = fmaxf(m2, e2); s2 = s2 * __expf(m2 - mn) + __expf(e2 - mn); m2 = mn;
        mn = fmaxf(m3, e3); s3 = s3 * __expf(m3 - mn) + __expf(e3 - mn); m3 = mn;
    }
#pragma unroll
    for (int o = 16; o; o >>= 1) {
        float mo, so, mn;
        mo = __shfl_xor_sync(FULLM, m0, o); so = __shfl_xor_sync(FULLM, s0, o);
        mn = fmaxf(m0, mo); s0 = s0 * __expf(m0 - mn) + so * __expf(mo - mn); m0 = mn;
        mo = __shfl_xor_sync(FULLM, m1, o); so = __shfl_xor_sync(FULLM, s1, o);
        mn = fmaxf(m1, mo); s1 = s1 * __expf(m1 - mn) + so * __expf(mo - mn); m1 = mn;
        mo = __shfl_xor_sync(FULLM, m2, o); so = __shfl_xor_sync(FULLM, s2, o);
        mn = fmaxf(m2, mo); s2 = s2 * __expf(m2 - mn) + so * __expf(mo - mn); m2 = mn;
        mo = __shfl_xor_sync(FULLM, m3, o); so = __shfl_xor_sync(FULLM, s3, o);
        mn = fmaxf(m3, mo); s3 = s3 * __expf(m3 - mn) + so * __expf(mo - mn); m3 = mn;
    }
    const float i0 = 0.25f / (s0 + EPS_SM);
    const float i1 = 0.25f / (s1 + EPS_SM);
    const float i2 = 0.25f / (s2 + EPS_SM);
    const float i3 = 0.25f / (s3 + EPS_SM);

    // pass 2: gather-aggregate, float2 (2 consecutive channels) per lane
    float accx = 0.f, accy = 0.f;
    const int c2 = 2 * lane;
    for (int base = start; base < end; base += 32) {
        int sl = base + lane;
        int sid = 0;
        float w0 = 0.f, w1 = 0.f, w2 = 0.f, w3 = 0.f;
        if (sl < end) {
            sid = g_srcid[sl];
            float4 al = *(const float4*)(g_al + 4 * sid);
            w0 = __expf(lrelu(al.x + ar.x) - m0) * i0;
            w1 = __expf(lrelu(al.y + ar.y) - m1) * i1;
            w2 = __expf(lrelu(al.z + ar.z) - m2) * i2;
            w3 = __expf(lrelu(al.w + ar.w) - m3) * i3;
        }
        int cnt = min(32, end - base);
        for (int j = 0; j < cnt; j++) {
            int sj = __shfl_sync(FULLM, sid, j);
            float u0 = __shfl_sync(FULLM, w0, j);
            float u1 = __shfl_sync(FULLM, w1, j);
            float u2 = __shfl_sync(FULLM, w2, j);
            float u3 = __shfl_sync(FULLM, w3, j);
            const float* hp = g_h + (size_t)sj * HC;
            float2 v0 = *(const float2*)&hp[c2];
            float2 v1 = *(const float2*)&hp[64 + c2];
            float2 v2 = *(const float2*)&hp[128 + c2];
            float2 v3 = *(const float2*)&hp[192 + c2];
            accx += v0.x * u0 + v1.x * u1 + v2.x * u2 + v3.x * u3;
            accy += v0.y * u0 + v1.y * u1 + v2.y * u2 + v3.y * u3;
        }
    }

    if (FINAL) {
        float2 bv = *(const float2*)&bias[c2];
        *(float2*)&out[(size_t)d * CC + c2] = make_float2(accx + bv.x, accy + bv.y);
    } else {
        *(float2*)&out[(size_t)d * CC + c2] = make_float2(accx, accy);
        atomicAdd(&sbn[c2],          accx);
        atomicAdd(&sbn[c2 + 1],      accy);
        atomicAdd(&sbn[64 + c2],     accx * accx);
        atomicAdd(&sbn[64 + c2 + 1], accy * accy);
        __syncthreads();
        if (threadIdx.x < 2 * CC) atomicAdd(&g_bn[threadIdx.x], sbn[threadIdx.x]);
    }
}

// ================= BN fold: stats -> per-channel scale/shift =================
__global__ void bn_prep_kernel(const float* __restrict__ gam,
                               const float* __restrict__ bet)
{
    int c = threadIdx.x;
    if (c >= CC) return;
    const float inv_n = 1.f / (float)NN;
    float mu = g_bn[c] * inv_n;
    float var = g_bn[64 + c] * inv_n - mu * mu;
    float s = rsqrtf(var + EPS_BN) * gam[c];
    g_scale[c] = s;
    g_shift[c] = bet[c] - mu * s;
}

// ================= host orchestration =================
extern "C" void kernel_launch(void* const* d_in, const int* in_sizes, int n_in,
                              void* d_out, int out_size)
{
    const float* x   = (const float*)d_in[0];
    const int*   ei  = (const int*)d_in[1];
    const float* W0  = (const float*)d_in[2];
    const float* as0 = (const float*)d_in[3];
    const float* ad0 = (const float*)d_in[4];
    const float* W1  = (const float*)d_in[6];
    const float* as1 = (const float*)d_in[7];
    const float* ad1 = (const float*)d_in[8];
    const float* W2  = (const float*)d_in[10];
    const float* as2 = (const float*)d_in[11];
    const float* ad2 = (const float*)d_in[12];
    const float* b2  = (const float*)d_in[13];
    const float* g0  = (const float*)d_in[14];
    const float* be0 = (const float*)d_in[15];
    const float* g1  = (const float*)d_in[16];
    const float* be1 = (const float*)d_in[17];
    float* out = (float*)d_out;

    float *acc_ptr, *bn_ptr, *al_ptr, *ar_ptr;
    int *deg_ptr;
    cudaGetSymbolAddress((void**)&acc_ptr, g_acc);
    cudaGetSymbolAddress((void**)&bn_ptr, g_bn);
    cudaGetSymbolAddress((void**)&al_ptr, g_al);
    cudaGetSymbolAddress((void**)&ar_ptr, g_ar);
    cudaGetSymbolAddress((void**)&deg_ptr, g_deg);

    const dim3 gemm_grid(4, (NN + 127) / 128);
    const int node_blocks = NN / 8;
    const int edge_blocks = (EE + 255) / 256;
    const size_t attn_bytes = (size_t)NN * HH * sizeof(float);

    // ---- CSR build (edge structure is layer-invariant) ----
    cudaMemsetAsync(deg_ptr, 0, NN * sizeof(int));
    hist_kernel<<<edge_blocks, 256>>>(ei);
    scan_kernel<<<1, 1024>>>();
    scatter_kernel<<<edge_blocks, 256>>>(ei);

    // ---- layer 0 ----
    cudaMemsetAsync(al_ptr, 0, attn_bytes);
    cudaMemsetAsync(ar_ptr, 0, attn_bytes);
    cudaMemsetAsync(bn_ptr, 0, 2 * CC * sizeof(float));
    mma_gemm_kernel<256, false><<<gemm_grid, 256>>>(x, W0, as0, ad0);
    node_kernel<false><<<node_blocks, 256>>>(acc_ptr, nullptr);
    bn_prep_kernel<<<1, 64>>>(g0, be0);

    // ---- layer 1 ----
    cudaMemsetAsync(al_ptr, 0, attn_bytes);
    cudaMemsetAsync(ar_ptr, 0, attn_bytes);
    cudaMemsetAsync(bn_ptr, 0, 2 * CC * sizeof(float));
    mma_gemm_kernel<64, true><<<gemm_grid, 256>>>(acc_ptr, W1, as1, ad1);
    node_kernel<false><<<node_blocks, 256>>>(acc_ptr, nullptr);
    bn_prep_kernel<<<1, 64>>>(g1, be1);

    // ---- layer 2 ----
    cudaMemsetAsync(al_ptr, 0, attn_bytes);
    cudaMemsetAsync(ar_ptr, 0, attn_bytes);
    mma_gemm_kernel<64, true><<<gemm_grid, 256>>>(acc_ptr, W2, as2, ad2);
    node_kernel<true><<<node_blocks, 256>>>(out, b2);
}

// round 12
// speedup vs baseline: 2.9393x; 1.1627x over previous
#include <cuda_runtime.h>
#include <cuda_fp16.h>
#include <math.h>

#define NN 50000
#define EE 800000
#define ET (EE + NN)
#define HH 4
#define CC 64
#define HC 256
#define NEG 0.2f
#define EPS_SM 1e-16f
#define EPS_BN 1e-5f
#define FULLM 0xffffffffu
#define NEG_BIG (-1e30f)

// ---------------- scratch ----------------
__device__ float g_h[NN * HC];      // transformed features [N,H,C]
__device__ float g_al[NN * HH];     // attn src terms (atomic-accumulated by GEMM)
__device__ float g_ar[NN * HH];
__device__ float g_acc[NN * CC];    // aggregation output / next-layer input
__device__ float g_bn[2 * CC];      // [0:64) sum, [64:128) sumsq
__device__ float g_scale[CC];       // BN folded scale
__device__ float g_shift[CC];       // BN folded shift
__device__ __half g_Bhi[256 * 256]; // pre-split weight matrix (hi)
__device__ __half g_Blo[256 * 256]; // pre-split weight matrix (lo)
__device__ int   g_deg[NN];
__device__ int   g_off[NN + 1];
__device__ int   g_cur[NN];
__device__ int   g_srcid[ET];       // CSR (by dst) source node ids

__device__ __forceinline__ float lrelu(float v) { return v > 0.f ? v : NEG * v; }

__device__ __forceinline__ unsigned sptr(const void* p) {
    return (unsigned)__cvta_generic_to_shared(p);
}

__device__ __forceinline__ unsigned pack2h(float a, float b) {
    __half2 h = __floats2half2_rn(a, b);
    return reinterpret_cast<unsigned&>(h);
}

// ================= CSR build (once per launch) =================
__global__ void hist_kernel(const int* __restrict__ ei)
{
    int e = blockIdx.x * blockDim.x + threadIdx.x;
    if (e < EE) atomicAdd(&g_deg[ei[EE + e]], 1);
}

// single-block exclusive scan; self-loop (+1 degree) folded in here
__global__ __launch_bounds__(1024) void scan_kernel()
{
    __shared__ int wsum[32];
    const int T = 1024;
    const int PER = (NN + T - 1) / T;
    int t = threadIdx.x;
    int base = t * PER;
    int s = 0;
    for (int i = 0; i < PER; i++) {
        int idx = base + i;
        if (idx < NN) s += g_deg[idx] + 1;
    }
    int lane = t & 31, w = t >> 5;
    int v = s;
#pragma unroll
    for (int o = 1; o < 32; o <<= 1) {
        int u = __shfl_up_sync(FULLM, v, o);
        if (lane >= o) v += u;
    }
    if (lane == 31) wsum[w] = v;
    __syncthreads();
    if (w == 0) {
        int ws = wsum[lane];
#pragma unroll
        for (int o = 1; o < 32; o <<= 1) {
            int u = __shfl_up_sync(FULLM, ws, o);
            if (lane >= o) ws += u;
        }
        wsum[lane] = ws;
    }
    __syncthreads();
    int run = v - s + (w > 0 ? wsum[w - 1] : 0);
    for (int i = 0; i < PER; i++) {
        int idx = base + i;
        if (idx < NN) {
            int dg = g_deg[idx] + 1;
            g_off[idx] = run;
            g_srcid[run] = idx;      // self loop occupies first slot
            g_cur[idx] = run + 1;
            run += dg;
        }
    }
    if (t == T - 1) g_off[NN] = ET;
}

__global__ void scatter_kernel(const int* __restrict__ ei)
{
    int e = blockIdx.x * blockDim.x + threadIdx.x;
    if (e >= EE) return;
    int s = ei[e], d = ei[EE + e];
    int pos = atomicAdd(&g_cur[d], 1);
    g_srcid[pos] = s;
}

// ================= B pre-split: fp32 -> (hi, lo) halves =================
__global__ void bsplit_kernel(const float* __restrict__ B, int n)
{
    int i = blockIdx.x * blockDim.x + threadIdx.x;
    if (i >= n) return;
    float v = B[i];
    __half hi = __float2half_rn(v);
    g_Bhi[i] = hi;
    g_Blo[i] = __float2half_rn(v - __half2float(hi));
}

// ================= tensor-core GEMM + fused BN(A) + fused attn epilogue ====
// C[N,256] = A[N,K] @ B[K,256], mma m16n8k16 fp16 3-term hi/lo split.
// Block tile 128x64, BK=32, 8 warps (4m x 2n). blockIdx.x == head index.
// Register double-buffered global loads; vectorized STS.128 smem fills;
// B comes pre-split from g_Bhi/g_Blo.
#define ASTR 40
#define BSTR 72

__device__ __forceinline__ void mma16816(float* c, const unsigned* a, const unsigned* b)
{
    asm volatile(
        "mma.sync.aligned.m16n8k16.row.col.f32.f16.f16.f32 "
        "{%0,%1,%2,%3}, {%4,%5,%6,%7}, {%8,%9}, {%0,%1,%2,%3};"
        : "+f"(c[0]), "+f"(c[1]), "+f"(c[2]), "+f"(c[3])
        : "r"(a[0]), "r"(a[1]), "r"(a[2]), "r"(a[3]), "r"(b[0]), "r"(b[1]));
}

__device__ __forceinline__ void ldm_x4(unsigned* r, unsigned addr)
{
    asm volatile("ldmatrix.sync.aligned.m8n8.x4.shared.b16 {%0,%1,%2,%3}, [%4];"
                 : "=r"(r[0]), "=r"(r[1]), "=r"(r[2]), "=r"(r[3]) : "r"(addr));
}

__device__ __forceinline__ void ldm_x2t(unsigned* r, unsigned addr)
{
    asm volatile("ldmatrix.sync.aligned.m8n8.x2.trans.shared.b16 {%0,%1}, [%2];"
                 : "=r"(r[0]), "=r"(r[1]) : "r"(addr));
}

template <int K, bool BN>
__global__ __launch_bounds__(256, 2) void mma_gemm_kernel(
    const float* __restrict__ A,
    const float* __restrict__ asrc, const float* __restrict__ adst)
{
    __shared__ __half As_hi[128][ASTR];
    __shared__ __half As_lo[128][ASTR];
    __shared__ __half Bs_hi[32][BSTR];
    __shared__ __half Bs_lo[32][BSTR];

    const int row0 = blockIdx.y * 128;
    const int bn0  = blockIdx.x * 64;
    const int tid  = threadIdx.x;
    const int lane = tid & 31;
    const int wid  = tid >> 5;
    const int warp_m = wid & 3;
    const int warp_n = wid >> 2;
    const int g  = lane >> 2;
    const int tq = lane & 3;

    float acc[2][4][4];
#pragma unroll
    for (int mi = 0; mi < 2; mi++)
#pragma unroll
        for (int ni = 0; ni < 4; ni++)
#pragma unroll
            for (int q = 0; q < 4; q++) acc[mi][ni][q] = 0.f;

    // global-load assignments
    const int arw = tid >> 1;            // A row 0..127
    const int ac0 = (tid & 1) * 16;      // A col base
    const int brw = tid >> 3;            // B row 0..31
    const int bc0 = (tid & 7) * 8;       // B col base (8 halves = 16B)

    const int gr = row0 + arw;
    const bool ok = gr < NN;
    const float* ap = A + (size_t)gr * K + ac0;
    const __half* bhp = g_Bhi + (size_t)brw * 256 + bn0 + bc0;
    const __half* blp = g_Blo + (size_t)brw * 256 + bn0 + bc0;
    const float4 zero4 = make_float4(0.f, 0.f, 0.f, 0.f);

    // ---- preload ktile 0 into registers ----
    float4 af[4];
    uint4 bh, bl;
#pragma unroll
    for (int v = 0; v < 4; v++)
        af[v] = ok ? *(const float4*)(ap + v * 4) : zero4;
    bh = *(const uint4*)bhp;
    bl = *(const uint4*)blp;

    for (int k0 = 0; k0 < K; k0 += 32) {
        if (k0) __syncthreads();   // prior ldmatrix consumers done

        // ---- store tile k0 (regs -> smem), BN+ReLU fold, hi/lo split ----
        {
            float val[16];
#pragma unroll
            for (int v = 0; v < 4; v++) {
                val[v * 4 + 0] = af[v].x;
                val[v * 4 + 1] = af[v].y;
                val[v * 4 + 2] = af[v].z;
                val[v * 4 + 3] = af[v].w;
            }
            if (BN && ok) {
#pragma unroll
                for (int i = 0; i < 16; i++) {
                    int c = k0 + ac0 + i;
                    val[i] = fmaxf(fmaf(val[i], g_scale[c], g_shift[c]), 0.f);
                }
            }
            float lo[16];
#pragma unroll
            for (int i = 0; i < 16; i++)
                lo[i] = val[i] - __half2float(__float2half_rn(val[i]));
            uint4 uh0, uh1, ul0, ul1;
            uh0.x = pack2h(val[0], val[1]);   uh0.y = pack2h(val[2], val[3]);
            uh0.z = pack2h(val[4], val[5]);   uh0.w = pack2h(val[6], val[7]);
            uh1.x = pack2h(val[8], val[9]);   uh1.y = pack2h(val[10], val[11]);
            uh1.z = pack2h(val[12], val[13]); uh1.w = pack2h(val[14], val[15]);
            ul0.x = pack2h(lo[0], lo[1]);     ul0.y = pack2h(lo[2], lo[3]);
            ul0.z = pack2h(lo[4], lo[5]);     ul0.w = pack2h(lo[6], lo[7]);
            ul1.x = pack2h(lo[8], lo[9]);     ul1.y = pack2h(lo[10], lo[11]);
            ul1.z = pack2h(lo[12], lo[13]);   ul1.w = pack2h(lo[14], lo[15]);
            *(uint4*)&As_hi[arw][ac0]     = uh0;
            *(uint4*)&As_hi[arw][ac0 + 8] = uh1;
            *(uint4*)&As_lo[arw][ac0]     = ul0;
            *(uint4*)&As_lo[arw][ac0 + 8] = ul1;
            *(uint4*)&Bs_hi[brw][bc0] = bh;
            *(uint4*)&Bs_lo[brw][bc0] = bl;
        }
        __syncthreads();

        // ---- prefetch tile k0+32 (LDGs overlap with mma below) ----
        if (k0 + 32 < K) {
            const int kn = k0 + 32;
#pragma unroll
            for (int v = 0; v < 4; v++)
                af[v] = ok ? *(const float4*)(ap + kn + v * 4) : zero4;
            bh = *(const uint4*)(bhp + (size_t)kn * 256);
            bl = *(const uint4*)(blp + (size_t)kn * 256);
        }

        // ---- mma on tile k0 ----
#pragma unroll
        for (int ks = 0; ks < 2; ks++) {
            unsigned ahi[2][4], alo[2][4], bhi[4][2], blo[4][2];
#pragma unroll
            for (int mi = 0; mi < 2; mi++) {
                int r = warp_m * 32 + mi * 16 + (lane & 15);
                int c = ks * 16 + (lane >> 4) * 8;
                ldm_x4(ahi[mi], sptr(&As_hi[r][c]));
                ldm_x4(alo[mi], sptr(&As_lo[r][c]));
            }
#pragma unroll
            for (int ni = 0; ni < 4; ni++) {
                int r = ks * 16 + (lane & 15);
                int c = warp_n * 32 + ni * 8;
                ldm_x2t(bhi[ni], sptr(&Bs_hi[r][c]));
                ldm_x2t(blo[ni], sptr(&Bs_lo[r][c]));
            }
#pragma unroll
            for (int mi = 0; mi < 2; mi++)
#pragma unroll
                for (int ni = 0; ni < 4; ni++) {
                    mma16816(acc[mi][ni], ahi[mi], bhi[ni]);
                    mma16816(acc[mi][ni], ahi[mi], blo[ni]);
                    mma16816(acc[mi][ni], alo[mi], bhi[ni]);
                }
        }
    }

    // ---- epilogue 1: write fp32 g_h ----
#pragma unroll
    for (int mi = 0; mi < 2; mi++) {
        int r = row0 + warp_m * 32 + mi * 16 + g;
#pragma unroll
        for (int ni = 0; ni < 4; ni++) {
            int c = bn0 + warp_n * 32 + ni * 8 + 2 * tq;
            if (r < NN)
                *(float2*)&g_h[(size_t)r * 256 + c] =
                    make_float2(acc[mi][ni][0], acc[mi][ni][1]);
            if (r + 8 < NN)
                *(float2*)&g_h[(size_t)(r + 8) * 256 + c] =
                    make_float2(acc[mi][ni][2], acc[mi][ni][3]);
        }
    }

    // ---- epilogue 2: fused attention coefficients for head = blockIdx.x ----
    {
        const int h = blockIdx.x;
        const float* asb = asrc + h * CC;
        const float* adb = adst + h * CC;
        float sl[2][2] = {{0.f, 0.f}, {0.f, 0.f}};
        float sr[2][2] = {{0.f, 0.f}, {0.f, 0.f}};
#pragma unroll
        for (int mi = 0; mi < 2; mi++)
#pragma unroll
            for (int ni = 0; ni < 4; ni++)
#pragma unroll
                for (int q = 0; q < 4; q++) {
                    int cl = warp_n * 32 + ni * 8 + 2 * tq + (q & 1);
                    float v = acc[mi][ni][q];
                    sl[mi][q >> 1] = fmaf(v, asb[cl], sl[mi][q >> 1]);
                    sr[mi][q >> 1] = fmaf(v, adb[cl], sr[mi][q >> 1]);
                }
#pragma unroll
        for (int mi = 0; mi < 2; mi++)
#pragma unroll
            for (int hf = 0; hf < 2; hf++) {
                float a = sl[mi][hf], b = sr[mi][hf];
                a += __shfl_xor_sync(FULLM, a, 1);
                a += __shfl_xor_sync(FULLM, a, 2);
                b += __shfl_xor_sync(FULLM, b, 1);
                b += __shfl_xor_sync(FULLM, b, 2);
                int r = row0 + warp_m * 32 + mi * 16 + g + hf * 8;
                if (tq == 0 && r < NN) {
                    atomicAdd(&g_al[r * 4 + h], a);
                    atomicAdd(&g_ar[r * 4 + h], b);
                }
            }
    }
}

// ================= fused softmax + aggregation: warp per dst node ==========
template <bool FINAL>
__global__ __launch_bounds__(256) void node_kernel(
    float* __restrict__ out, const float* __restrict__ bias)
{
    __shared__ float sbn[2 * CC];
    if (!FINAL) {
        if (threadIdx.x < 2 * CC) sbn[threadIdx.x] = 0.f;
        __syncthreads();
    }

    const int d    = blockIdx.x * 8 + (threadIdx.x >> 5);
    const int lane = threadIdx.x & 31;
    const int start = g_off[d];
    const int end   = g_off[d + 1];
    const float4 ar = *(const float4*)(g_ar + 4 * d);

    // pass 1: online softmax per head (finite sentinel avoids NaN on empty lanes)
    float m0 = NEG_BIG, m1 = NEG_BIG, m2 = NEG_BIG, m3 = NEG_BIG;
    float s0 = 0.f, s1 = 0.f, s2 = 0.f, s3 = 0.f;
    for (int sl = start + lane; sl < end; sl += 32) {
        int s = g_srcid[sl];
        float4 al = *(const float4*)(g_al + 4 * s);
        float e0 = lrelu(al.x + ar.x);
        float e1 = lrelu(al.y + ar.y);
        float e2 = lrelu(al.z + ar.z);
        float e3 = lrelu(al.w + ar.w);
        float mn;
        mn = fmaxf(m0, e0); s0 = s0 * __expf(m0 - mn) + __expf(e0 - mn); m0 = mn;
        mn = fmaxf(m1, e1); s1 = s1 * __expf(m1 - mn) + __expf(e1 - mn); m1 = mn;
        mn = fmaxf(m2, e2); s2 = s2 * __expf(m2 - mn) + __expf(e2 - mn); m2 = mn;
        mn = fmaxf(m3, e3); s3 = s3 * __expf(m3 - mn) + __expf(e3 - mn); m3 = mn;
    }
#pragma unroll
    for (int o = 16; o; o >>= 1) {
        float mo, so, mn;
        mo = __shfl_xor_sync(FULLM, m0, o); so = __shfl_xor_sync(FULLM, s0, o);
        mn = fmaxf(m0, mo); s0 = s0 * __expf(m0 - mn) + so * __expf(mo - mn); m0 = mn;
        mo = __shfl_xor_sync(FULLM, m1, o); so = __shfl_xor_sync(FULLM, s1, o);
        mn = fmaxf(m1, mo); s1 = s1 * __expf(m1 - mn) + so * __expf(mo - mn); m1 = mn;
        mo = __shfl_xor_sync(FULLM, m2, o); so = __shfl_xor_sync(FULLM, s2, o);
        mn = fmaxf(m2, mo); s2 = s2 * __expf(m2 - mn) + so * __expf(mo - mn); m2 = mn;
        mo = __shfl_xor_sync(FULLM, m3, o); so = __shfl_xor_sync(FULLM, s3, o);
        mn = fmaxf(m3, mo); s3 = s3 * __expf(m3 - mn) + so * __expf(mo - mn); m3 = mn;
    }
    const float i0 = 0.25f / (s0 + EPS_SM);
    const float i1 = 0.25f / (s1 + EPS_SM);
    const float i2 = 0.25f / (s2 + EPS_SM);
    const float i3 = 0.25f / (s3 + EPS_SM);

    // pass 2: gather-aggregate, float2 (2 consecutive channels) per lane
    float accx = 0.f, accy = 0.f;
    const int c2 = 2 * lane;
    for (int base = start; base < end; base += 32) {
        int sl = base + lane;
        int sid = 0;
        float w0 = 0.f, w1 = 0.f, w2 = 0.f, w3 = 0.f;
        if (sl < end) {
            sid = g_srcid[sl];
            float4 al = *(const float4*)(g_al + 4 * sid);
            w0 = __expf(lrelu(al.x + ar.x) - m0) * i0;
            w1 = __expf(lrelu(al.y + ar.y) - m1) * i1;
            w2 = __expf(lrelu(al.z + ar.z) - m2) * i2;
            w3 = __expf(lrelu(al.w + ar.w) - m3) * i3;
        }
        int cnt = min(32, end - base);
        for (int j = 0; j < cnt; j++) {
            int sj = __shfl_sync(FULLM, sid, j);
            float u0 = __shfl_sync(FULLM, w0, j);
            float u1 = __shfl_sync(FULLM, w1, j);
            float u2 = __shfl_sync(FULLM, w2, j);
            float u3 = __shfl_sync(FULLM, w3, j);
            const float* hp = g_h + (size_t)sj * HC;
            float2 v0 = *(const float2*)&hp[c2];
            float2 v1 = *(const float2*)&hp[64 + c2];
            float2 v2 = *(const float2*)&hp[128 + c2];
            float2 v3 = *(const float2*)&hp[192 + c2];
            accx += v0.x * u0 + v1.x * u1 + v2.x * u2 + v3.x * u3;
            accy += v0.y * u0 + v1.y * u1 + v2.y * u2 + v3.y * u3;
        }
    }

    if (FINAL) {
        float2 bv = *(const float2*)&bias[c2];
        *(float2*)&out[(size_t)d * CC + c2] = make_float2(accx + bv.x, accy + bv.y);
    } else {
        *(float2*)&out[(size_t)d * CC + c2] = make_float2(accx, accy);
        atomicAdd(&sbn[c2],          accx);
        atomicAdd(&sbn[c2 + 1],      accy);
        atomicAdd(&sbn[64 + c2],     accx * accx);
        atomicAdd(&sbn[64 + c2 + 1], accy * accy);
        __syncthreads();
        if (threadIdx.x < 2 * CC) atomicAdd(&g_bn[threadIdx.x], sbn[threadIdx.x]);
    }
}

// ================= BN fold: stats -> per-channel scale/shift =================
__global__ void bn_prep_kernel(const float* __restrict__ gam,
                               const float* __restrict__ bet)
{
    int c = threadIdx.x;
    if (c >= CC) return;
    const float inv_n = 1.f / (float)NN;
    float mu = g_bn[c] * inv_n;
    float var = g_bn[64 + c] * inv_n - mu * mu;
    float s = rsqrtf(var + EPS_BN) * gam[c];
    g_scale[c] = s;
    g_shift[c] = bet[c] - mu * s;
}

// ================= host orchestration =================
extern "C" void kernel_launch(void* const* d_in, const int* in_sizes, int n_in,
                              void* d_out, int out_size)
{
    const float* x   = (const float*)d_in[0];
    const int*   ei  = (const int*)d_in[1];
    const float* W0  = (const float*)d_in[2];
    const float* as0 = (const float*)d_in[3];
    const float* ad0 = (const float*)d_in[4];
    const float* W1  = (const float*)d_in[6];
    const float* as1 = (const float*)d_in[7];
    const float* ad1 = (const float*)d_in[8];
    const float* W2  = (const float*)d_in[10];
    const float* as2 = (const float*)d_in[11];
    const float* ad2 = (const float*)d_in[12];
    const float* b2  = (const float*)d_in[13];
    const float* g0  = (const float*)d_in[14];
    const float* be0 = (const float*)d_in[15];
    const float* g1  = (const float*)d_in[16];
    const float* be1 = (const float*)d_in[17];
    float* out = (float*)d_out;

    float *acc_ptr, *bn_ptr, *al_ptr, *ar_ptr;
    int *deg_ptr;
    cudaGetSymbolAddress((void**)&acc_ptr, g_acc);
    cudaGetSymbolAddress((void**)&bn_ptr, g_bn);
    cudaGetSymbolAddress((void**)&al_ptr, g_al);
    cudaGetSymbolAddress((void**)&ar_ptr, g_ar);
    cudaGetSymbolAddress((void**)&deg_ptr, g_deg);

    const dim3 gemm_grid(4, (NN + 127) / 128);
    const int node_blocks = NN / 8;
    const int edge_blocks = (EE + 255) / 256;
    const size_t attn_bytes = (size_t)NN * HH * sizeof(float);

    // ---- CSR build (edge structure is layer-invariant) ----
    cudaMemsetAsync(deg_ptr, 0, NN * sizeof(int));
    hist_kernel<<<edge_blocks, 256>>>(ei);
    scan_kernel<<<1, 1024>>>();
    scatter_kernel<<<edge_blocks, 256>>>(ei);

    // ---- layer 0 ----
    cudaMemsetAsync(al_ptr, 0, attn_bytes);
    cudaMemsetAsync(ar_ptr, 0, attn_bytes);
    cudaMemsetAsync(bn_ptr, 0, 2 * CC * sizeof(float));
    bsplit_kernel<<<(256 * 256 + 255) / 256, 256>>>(W0, 256 * 256);
    mma_gemm_kernel<256, false><<<gemm_grid, 256>>>(x, as0, ad0);
    node_kernel<false><<<node_blocks, 256>>>(acc_ptr, nullptr);
    bn_prep_kernel<<<1, 64>>>(g0, be0);

    // ---- layer 1 ----
    cudaMemsetAsync(al_ptr, 0, attn_bytes);
    cudaMemsetAsync(ar_ptr, 0, attn_bytes);
    cudaMemsetAsync(bn_ptr, 0, 2 * CC * sizeof(float));
    bsplit_kernel<<<(64 * 256 + 255) / 256, 256>>>(W1, 64 * 256);
    mma_gemm_kernel<64, true><<<gemm_grid, 256>>>(acc_ptr, as1, ad1);
    node_kernel<false><<<node_blocks, 256>>>(acc_ptr, nullptr);
    bn_prep_kernel<<<1, 64>>>(g1, be1);

    // ---- layer 2 ----
    cudaMemsetAsync(al_ptr, 0, attn_bytes);
    cudaMemsetAsync(ar_ptr, 0, attn_bytes);
    bsplit_kernel<<<(64 * 256 + 255) / 256, 256>>>(W2, 64 * 256);
    mma_gemm_kernel<64, true><<<gemm_grid, 256>>>(acc_ptr, as2, ad2);
    node_kernel<true><<<node_blocks, 256>>>(out, b2);
}

// round 15
// speedup vs baseline: 2.9403x; 1.0004x over previous
#include <cuda_runtime.h>
#include <cuda_fp16.h>
#include <math.h>

#define NN 50000
#define EE 800000
#define ET (EE + NN)
#define HH 4
#define CC 64
#define HC 256
#define NEG 0.2f
#define EPS_SM 1e-16f
#define EPS_BN 1e-5f
#define FULLM 0xffffffffu
#define NEG_BIG (-1e30f)

// ---------------- scratch ----------------
// message storage: fp16, layout [n][c_pair(32)][head(4)] as half2 -> one
// LDG.128 per lane fetches (4 heads x 2 channels); warp reads 512B contiguous.
__device__ __half2 g_hh[NN * 128];
__device__ float g_al[NN * HH];     // attn src terms (atomic-accumulated by GEMM)
__device__ float g_ar[NN * HH];
__device__ float g_acc[NN * CC];    // aggregation output / next-layer input
__device__ float g_bn[2 * CC];      // [0:64) sum, [64:128) sumsq
__device__ float g_scale[CC];       // BN folded scale
__device__ float g_shift[CC];       // BN folded shift
__device__ __half g_Bhi[256 * 256]; // pre-split weight matrix (hi)
__device__ __half g_Blo[256 * 256]; // pre-split weight matrix (lo)
__device__ int   g_deg[NN];
__device__ int   g_off[NN + 1];
__device__ int   g_cur[NN];
__device__ int   g_srcid[ET];       // CSR (by dst) source node ids

__device__ __forceinline__ float lrelu(float v) { return v > 0.f ? v : NEG * v; }

__device__ __forceinline__ unsigned sptr(const void* p) {
    return (unsigned)__cvta_generic_to_shared(p);
}

__device__ __forceinline__ unsigned pack2h(float a, float b) {
    __half2 h = __floats2half2_rn(a, b);
    return reinterpret_cast<unsigned&>(h);
}

// ================= CSR build (once per launch) =================
__global__ void hist_kernel(const int* __restrict__ ei)
{
    int e = blockIdx.x * blockDim.x + threadIdx.x;
    if (e < EE) atomicAdd(&g_deg[ei[EE + e]], 1);
}

__global__ __launch_bounds__(1024) void scan_kernel()
{
    __shared__ int wsum[32];
    const int T = 1024;
    const int PER = (NN + T - 1) / T;
    int t = threadIdx.x;
    int base = t * PER;
    int s = 0;
    for (int i = 0; i < PER; i++) {
        int idx = base + i;
        if (idx < NN) s += g_deg[idx] + 1;
    }
    int lane = t & 31, w = t >> 5;
    int v = s;
#pragma unroll
    for (int o = 1; o < 32; o <<= 1) {
        int u = __shfl_up_sync(FULLM, v, o);
        if (lane >= o) v += u;
    }
    if (lane == 31) wsum[w] = v;
    __syncthreads();
    if (w == 0) {
        int ws = wsum[lane];
#pragma unroll
        for (int o = 1; o < 32; o <<= 1) {
            int u = __shfl_up_sync(FULLM, ws, o);
            if (lane >= o) ws += u;
        }
        wsum[lane] = ws;
    }
    __syncthreads();
    int run = v - s + (w > 0 ? wsum[w - 1] : 0);
    for (int i = 0; i < PER; i++) {
        int idx = base + i;
        if (idx < NN) {
            int dg = g_deg[idx] + 1;
            g_off[idx] = run;
            g_srcid[run] = idx;      // self loop occupies first slot
            g_cur[idx] = run + 1;
            run += dg;
        }
    }
    if (t == T - 1) g_off[NN] = ET;
}

__global__ void scatter_kernel(const int* __restrict__ ei)
{
    int e = blockIdx.x * blockDim.x + threadIdx.x;
    if (e >= EE) return;
    int s = ei[e], d = ei[EE + e];
    int pos = atomicAdd(&g_cur[d], 1);
    g_srcid[pos] = s;
}

// ================= B pre-split: fp32 -> (hi, lo) halves =================
__global__ void bsplit_kernel(const float* __restrict__ B, int n)
{
    int i = blockIdx.x * blockDim.x + threadIdx.x;
    if (i >= n) return;
    float v = B[i];
    __half hi = __float2half_rn(v);
    g_Bhi[i] = hi;
    g_Blo[i] = __float2half_rn(v - __half2float(hi));
}

// ================= tensor-core GEMM + fused BN(A) + fused attn epilogue ====
// C[N,256] = A[N,K] @ B[K,256], mma m16n8k16 fp16 3-term hi/lo split.
// Block tile 128x64, BK=32, 8 warps (4m x 2n). blockIdx.x == head index.
// Epilogue: fp16 messages to g_hh + full attn dot products (2 atomic
// contributors per (row,head): order-independent fp add).
#define ASTR 40
#define BSTR 72

__device__ __forceinline__ void mma16816(float* c, const unsigned* a, const unsigned* b)
{
    asm volatile(
        "mma.sync.aligned.m16n8k16.row.col.f32.f16.f16.f32 "
        "{%0,%1,%2,%3}, {%4,%5,%6,%7}, {%8,%9}, {%0,%1,%2,%3};"
        : "+f"(c[0]), "+f"(c[1]), "+f"(c[2]), "+f"(c[3])
        : "r"(a[0]), "r"(a[1]), "r"(a[2]), "r"(a[3]), "r"(b[0]), "r"(b[1]));
}

__device__ __forceinline__ void ldm_x4(unsigned* r, unsigned addr)
{
    asm volatile("ldmatrix.sync.aligned.m8n8.x4.shared.b16 {%0,%1,%2,%3}, [%4];"
                 : "=r"(r[0]), "=r"(r[1]), "=r"(r[2]), "=r"(r[3]) : "r"(addr));
}

__device__ __forceinline__ void ldm_x2t(unsigned* r, unsigned addr)
{
    asm volatile("ldmatrix.sync.aligned.m8n8.x2.trans.shared.b16 {%0,%1}, [%2];"
                 : "=r"(r[0]), "=r"(r[1]) : "r"(addr));
}

template <int K, bool BN>
__global__ __launch_bounds__(256, 2) void mma_gemm_kernel(
    const float* __restrict__ A,
    const float* __restrict__ asrc, const float* __restrict__ adst)
{
    __shared__ __half As_hi[128][ASTR];
    __shared__ __half As_lo[128][ASTR];
    __shared__ __half Bs_hi[32][BSTR];
    __shared__ __half Bs_lo[32][BSTR];

    const int row0 = blockIdx.y * 128;
    const int bn0  = blockIdx.x * 64;
    const int tid  = threadIdx.x;
    const int lane = tid & 31;
    const int wid  = tid >> 5;
    const int warp_m = wid & 3;
    const int warp_n = wid >> 2;
    const int g  = lane >> 2;
    const int tq = lane & 3;

    float acc[2][4][4];
#pragma unroll
    for (int mi = 0; mi < 2; mi++)
#pragma unroll
        for (int ni = 0; ni < 4; ni++)
#pragma unroll
            for (int q = 0; q < 4; q++) acc[mi][ni][q] = 0.f;

    const int arw = tid >> 1;
    const int ac0 = (tid & 1) * 16;
    const int brw = tid >> 3;
    const int bc0 = (tid & 7) * 8;

    const int gr = row0 + arw;
    const bool ok = gr < NN;
    const float* ap = A + (size_t)gr * K + ac0;
    const __half* bhp = g_Bhi + (size_t)brw * 256 + bn0 + bc0;
    const __half* blp = g_Blo + (size_t)brw * 256 + bn0 + bc0;
    const float4 zero4 = make_float4(0.f, 0.f, 0.f, 0.f);

    float4 af[4];
    uint4 bh, bl;
#pragma unroll
    for (int v = 0; v < 4; v++)
        af[v] = ok ? *(const float4*)(ap + v * 4) : zero4;
    bh = *(const uint4*)bhp;
    bl = *(const uint4*)blp;

    for (int k0 = 0; k0 < K; k0 += 32) {
        if (k0) __syncthreads();

        {
            float val[16];
#pragma unroll
            for (int v = 0; v < 4; v++) {
                val[v * 4 + 0] = af[v].x;
                val[v * 4 + 1] = af[v].y;
                val[v * 4 + 2] = af[v].z;
                val[v * 4 + 3] = af[v].w;
            }
            if (BN && ok) {
#pragma unroll
                for (int i = 0; i < 16; i++) {
                    int c = k0 + ac0 + i;
                    val[i] = fmaxf(fmaf(val[i], g_scale[c], g_shift[c]), 0.f);
                }
            }
            float lo[16];
#pragma unroll
            for (int i = 0; i < 16; i++)
                lo[i] = val[i] - __half2float(__float2half_rn(val[i]));
            uint4 uh0, uh1, ul0, ul1;
            uh0.x = pack2h(val[0], val[1]);   uh0.y = pack2h(val[2], val[3]);
            uh0.z = pack2h(val[4], val[5]);   uh0.w = pack2h(val[6], val[7]);
            uh1.x = pack2h(val[8], val[9]);   uh1.y = pack2h(val[10], val[11]);
            uh1.z = pack2h(val[12], val[13]); uh1.w = pack2h(val[14], val[15]);
            ul0.x = pack2h(lo[0], lo[1]);     ul0.y = pack2h(lo[2], lo[3]);
            ul0.z = pack2h(lo[4], lo[5]);     ul0.w = pack2h(lo[6], lo[7]);
            ul1.x = pack2h(lo[8], lo[9]);     ul1.y = pack2h(lo[10], lo[11]);
            ul1.z = pack2h(lo[12], lo[13]);   ul1.w = pack2h(lo[14], lo[15]);
            *(uint4*)&As_hi[arw][ac0]     = uh0;
            *(uint4*)&As_hi[arw][ac0 + 8] = uh1;
            *(uint4*)&As_lo[arw][ac0]     = ul0;
            *(uint4*)&As_lo[arw][ac0 + 8] = ul1;
            *(uint4*)&Bs_hi[brw][bc0] = bh;
            *(uint4*)&Bs_lo[brw][bc0] = bl;
        }
        __syncthreads();

        if (k0 + 32 < K) {
            const int kn = k0 + 32;
#pragma unroll
            for (int v = 0; v < 4; v++)
                af[v] = ok ? *(const float4*)(ap + kn + v * 4) : zero4;
            bh = *(const uint4*)(bhp + (size_t)kn * 256);
            bl = *(const uint4*)(blp + (size_t)kn * 256);
        }

#pragma unroll
        for (int ks = 0; ks < 2; ks++) {
            unsigned ahi[2][4], alo[2][4], bhi[4][2], blo[4][2];
#pragma unroll
            for (int mi = 0; mi < 2; mi++) {
                int r = warp_m * 32 + mi * 16 + (lane & 15);
                int c = ks * 16 + (lane >> 4) * 8;
                ldm_x4(ahi[mi], sptr(&As_hi[r][c]));
                ldm_x4(alo[mi], sptr(&As_lo[r][c]));
            }
#pragma unroll
            for (int ni = 0; ni < 4; ni++) {
                int r = ks * 16 + (lane & 15);
                int c = warp_n * 32 + ni * 8;
                ldm_x2t(bhi[ni], sptr(&Bs_hi[r][c]));
                ldm_x2t(blo[ni], sptr(&Bs_lo[r][c]));
            }
#pragma unroll
            for (int mi = 0; mi < 2; mi++)
#pragma unroll
                for (int ni = 0; ni < 4; ni++) {
                    mma16816(acc[mi][ni], ahi[mi], bhi[ni]);
                    mma16816(acc[mi][ni], ahi[mi], blo[ni]);
                    mma16816(acc[mi][ni], alo[mi], bhi[ni]);
                }
        }
    }

    // ---- epilogue 1: write fp16 messages to g_hh[n][c_pair][head] ----
    {
        const int h = blockIdx.x;
#pragma unroll
        for (int mi = 0; mi < 2; mi++) {
            int r = row0 + warp_m * 32 + mi * 16 + g;
#pragma unroll
            for (int ni = 0; ni < 4; ni++) {
                int cp = warp_n * 16 + ni * 4 + tq;     // channel pair 0..31
                if (r < NN)
                    g_hh[(size_t)r * 128 + cp * 4 + h] =
                        __floats2half2_rn(acc[mi][ni][0], acc[mi][ni][1]);
                if (r + 8 < NN)
                    g_hh[(size_t)(r + 8) * 128 + cp * 4 + h] =
                        __floats2half2_rn(acc[mi][ni][2], acc[mi][ni][3]);
            }
        }
    }

    // ---- epilogue 2: fused attention coefficients for head = blockIdx.x ----
    {
        const int h = blockIdx.x;
        const float* asb = asrc + h * CC;
        const float* adb = adst + h * CC;
        float sl[2][2] = {{0.f, 0.f}, {0.f, 0.f}};
        float sr[2][2] = {{0.f, 0.f}, {0.f, 0.f}};
#pragma unroll
        for (int mi = 0; mi < 2; mi++)
#pragma unroll
            for (int ni = 0; ni < 4; ni++)
#pragma unroll
                for (int q = 0; q < 4; q++) {
                    int cl = warp_n * 32 + ni * 8 + 2 * tq + (q & 1);
                    float v = acc[mi][ni][q];
                    sl[mi][q >> 1] = fmaf(v, asb[cl], sl[mi][q >> 1]);
                    sr[mi][q >> 1] = fmaf(v, adb[cl], sr[mi][q >> 1]);
                }
#pragma unroll
        for (int mi = 0; mi < 2; mi++)
#pragma unroll
            for (int hf = 0; hf < 2; hf++) {
                float a = sl[mi][hf], b = sr[mi][hf];
                a += __shfl_xor_sync(FULLM, a, 1);
                a += __shfl_xor_sync(FULLM, a, 2);
                b += __shfl_xor_sync(FULLM, b, 1);
                b += __shfl_xor_sync(FULLM, b, 2);
                int r = row0 + warp_m * 32 + mi * 16 + g + hf * 8;
                if (tq == 0 && r < NN) {
                    atomicAdd(&g_al[r * 4 + h], a);
                    atomicAdd(&g_ar[r * 4 + h], b);
                }
            }
    }
}

// ================= fused softmax + aggregation: warp per dst node ==========
template <bool FINAL>
__global__ __launch_bounds__(256) void node_kernel(
    float* __restrict__ out, const float* __restrict__ bias)
{
    __shared__ float sbn[2 * CC];
    if (!FINAL) {
        if (threadIdx.x < 2 * CC) sbn[threadIdx.x] = 0.f;
        __syncthreads();
    }

    const int d    = blockIdx.x * 8 + (threadIdx.x >> 5);
    const int lane = threadIdx.x & 31;
    const int start = g_off[d];
    const int end   = g_off[d + 1];
    const float4 ar = *(const float4*)(g_ar + 4 * d);

    // pass 1: online softmax per head (finite sentinel avoids NaN on empty lanes)
    float m0 = NEG_BIG, m1 = NEG_BIG, m2 = NEG_BIG, m3 = NEG_BIG;
    float s0 = 0.f, s1 = 0.f, s2 = 0.f, s3 = 0.f;
    for (int sl = start + lane; sl < end; sl += 32) {
        int s = g_srcid[sl];
        float4 al = *(const float4*)(g_al + 4 * s);
        float e0 = lrelu(al.x + ar.x);
        float e1 = lrelu(al.y + ar.y);
        float e2 = lrelu(al.z + ar.z);
        float e3 = lrelu(al.w + ar.w);
        float mn;
        mn = fmaxf(m0, e0); s0 = s0 * __expf(m0 - mn) + __expf(e0 - mn); m0 = mn;
        mn = fmaxf(m1, e1); s1 = s1 * __expf(m1 - mn) + __expf(e1 - mn); m1 = mn;
        mn = fmaxf(m2, e2); s2 = s2 * __expf(m2 - mn) + __expf(e2 - mn); m2 = mn;
        mn = fmaxf(m3, e3); s3 = s3 * __expf(m3 - mn) + __expf(e3 - mn); m3 = mn;
    }
#pragma unroll
    for (int o = 16; o; o >>= 1) {
        float mo, so, mn;
        mo = __shfl_xor_sync(FULLM, m0, o); so = __shfl_xor_sync(FULLM, s0, o);
        mn = fmaxf(m0, mo); s0 = s0 * __expf(m0 - mn) + so * __expf(mo - mn); m0 = mn;
        mo = __shfl_xor_sync(FULLM, m1, o); so = __shfl_xor_sync(FULLM, s1, o);
        mn = fmaxf(m1, mo); s1 = s1 * __expf(m1 - mn) + so * __expf(mo - mn); m1 = mn;
        mo = __shfl_xor_sync(FULLM, m2, o); so = __shfl_xor_sync(FULLM, s2, o);
        mn = fmaxf(m2, mo); s2 = s2 * __expf(m2 - mn) + so * __expf(mo - mn); m2 = mn;
        mo = __shfl_xor_sync(FULLM, m3, o); so = __shfl_xor_sync(FULLM, s3, o);
        mn = fmaxf(m3, mo); s3 = s3 * __expf(m3 - mn) + so * __expf(mo - mn); m3 = mn;
    }
    const float i0 = 0.25f / (s0 + EPS_SM);
    const float i1 = 0.25f / (s1 + EPS_SM);
    const float i2 = 0.25f / (s2 + EPS_SM);
    const float i3 = 0.25f / (s3 + EPS_SM);

    // pass 2: gather-aggregate; one LDG.128 per lane per edge gives
    // (4 heads x 2 channels) fp16 values for channel pair = lane.
    float accx = 0.f, accy = 0.f;
    const __half2* hrow = g_hh + (size_t)lane * 4;
    for (int base = start; base < end; base += 32) {
        int sl = base + lane;
        int sid = 0;
        float w0 = 0.f, w1 = 0.f, w2 = 0.f, w3 = 0.f;
        if (sl < end) {
            sid = g_srcid[sl];
            float4 al = *(const float4*)(g_al + 4 * sid);
            w0 = __expf(lrelu(al.x + ar.x) - m0) * i0;
            w1 = __expf(lrelu(al.y + ar.y) - m1) * i1;
            w2 = __expf(lrelu(al.z + ar.z) - m2) * i2;
            w3 = __expf(lrelu(al.w + ar.w) - m3) * i3;
        }
        int cnt = min(32, end - base);
        for (int j = 0; j < cnt; j++) {
            int sj = __shfl_sync(FULLM, sid, j);
            float u0 = __shfl_sync(FULLM, w0, j);
            float u1 = __shfl_sync(FULLM, w1, j);
            float u2 = __shfl_sync(FULLM, w2, j);
            float u3 = __shfl_sync(FULLM, w3, j);
            __half2 hv[4];
            *(uint4*)hv = *(const uint4*)(hrow + (size_t)sj * 128);
            float2 f0 = __half22float2(hv[0]);
            float2 f1 = __half22float2(hv[1]);
            float2 f2 = __half22float2(hv[2]);
            float2 f3 = __half22float2(hv[3]);
            accx += f0.x * u0 + f1.x * u1 + f2.x * u2 + f3.x * u3;
            accy += f0.y * u0 + f1.y * u1 + f2.y * u2 + f3.y * u3;
        }
    }

    const int c2 = 2 * lane;
    if (FINAL) {
        float2 bv = *(const float2*)&bias[c2];
        *(float2*)&out[(size_t)d * CC + c2] = make_float2(accx + bv.x, accy + bv.y);
    } else {
        *(float2*)&out[(size_t)d * CC + c2] = make_float2(accx, accy);
        atomicAdd(&sbn[c2],          accx);
        atomicAdd(&sbn[c2 + 1],      accy);
        atomicAdd(&sbn[64 + c2],     accx * accx);
        atomicAdd(&sbn[64 + c2 + 1], accy * accy);
        __syncthreads();
        if (threadIdx.x < 2 * CC) atomicAdd(&g_bn[threadIdx.x], sbn[threadIdx.x]);
    }
}

// ================= BN fold: stats -> per-channel scale/shift =================
__global__ void bn_prep_kernel(const float* __restrict__ gam,
                               const float* __restrict__ bet)
{
    int c = threadIdx.x;
    if (c >= CC) return;
    const float inv_n = 1.f / (float)NN;
    float mu = g_bn[c] * inv_n;
    float var = g_bn[64 + c] * inv_n - mu * mu;
    float s = rsqrtf(var + EPS_BN) * gam[c];
    g_scale[c] = s;
    g_shift[c] = bet[c] - mu * s;
}

// ================= host orchestration =================
extern "C" void kernel_launch(void* const* d_in, const int* in_sizes, int n_in,
                              void* d_out, int out_size)
{
    const float* x   = (const float*)d_in[0];
    const int*   ei  = (const int*)d_in[1];
    const float* W0  = (const float*)d_in[2];
    const float* as0 = (const float*)d_in[3];
    const float* ad0 = (const float*)d_in[4];
    const float* W1  = (const float*)d_in[6];
    const float* as1 = (const float*)d_in[7];
    const float* ad1 = (const float*)d_in[8];
    const float* W2  = (const float*)d_in[10];
    const float* as2 = (const float*)d_in[11];
    const float* ad2 = (const float*)d_in[12];
    const float* b2  = (const float*)d_in[13];
    const float* g0  = (const float*)d_in[14];
    const float* be0 = (const float*)d_in[15];
    const float* g1  = (const float*)d_in[16];
    const float* be1 = (const float*)d_in[17];
    float* out = (float*)d_out;

    float *acc_ptr, *bn_ptr, *al_ptr, *ar_ptr;
    int *deg_ptr;
    cudaGetSymbolAddress((void**)&acc_ptr, g_acc);
    cudaGetSymbolAddress((void**)&bn_ptr, g_bn);
    cudaGetSymbolAddress((void**)&al_ptr, g_al);
    cudaGetSymbolAddress((void**)&ar_ptr, g_ar);
    cudaGetSymbolAddress((void**)&deg_ptr, g_deg);

    const dim3 gemm_grid(4, (NN + 127) / 128);
    const int node_blocks = NN / 8;
    const int edge_blocks = (EE + 255) / 256;
    const size_t attn_bytes = (size_t)NN * HH * sizeof(float);

    // ---- CSR build (edge structure is layer-invariant) ----
    cudaMemsetAsync(deg_ptr, 0, NN * sizeof(int));
    hist_kernel<<<edge_blocks, 256>>>(ei);
    scan_kernel<<<1, 1024>>>();
    scatter_kernel<<<edge_blocks, 256>>>(ei);

    // ---- layer 0 ----
    cudaMemsetAsync(al_ptr, 0, attn_bytes);
    cudaMemsetAsync(ar_ptr, 0, attn_bytes);
    cudaMemsetAsync(bn_ptr, 0, 2 * CC * sizeof(float));
    bsplit_kernel<<<(256 * 256 + 255) / 256, 256>>>(W0, 256 * 256);
    mma_gemm_kernel<256, false><<<gemm_grid, 256>>>(x, as0, ad0);
    node_kernel<false><<<node_blocks, 256>>>(acc_ptr, nullptr);
    bn_prep_kernel<<<1, 64>>>(g0, be0);

    // ---- layer 1 ----
    cudaMemsetAsync(al_ptr, 0, attn_bytes);
    cudaMemsetAsync(ar_ptr, 0, attn_bytes);
    cudaMemsetAsync(bn_ptr, 0, 2 * CC * sizeof(float));
    bsplit_kernel<<<(64 * 256 + 255) / 256, 256>>>(W1, 64 * 256);
    mma_gemm_kernel<64, true><<<gemm_grid, 256>>>(acc_ptr, as1, ad1);
    node_kernel<false><<<node_blocks, 256>>>(acc_ptr, nullptr);
    bn_prep_kernel<<<1, 64>>>(g1, be1);

    // ---- layer 2 ----
    cudaMemsetAsync(al_ptr, 0, attn_bytes);
    cudaMemsetAsync(ar_ptr, 0, attn_bytes);
    bsplit_kernel<<<(64 * 256 + 255) / 256, 256>>>(W2, 64 * 256);
    mma_gemm_kernel<64, true><<<gemm_grid, 256>>>(acc_ptr, as2, ad2);
    node_kernel<true><<<node_blocks, 256>>>(out, b2);
}

// round 17
// speedup vs baseline: 3.3897x; 1.1528x over previous
#include <cuda_runtime.h>
#include <cuda_fp16.h>
#include <math.h>

#define NN 50000
#define EE 800000
#define ET (EE + NN)
#define HH 4
#define CC 64
#define HC 256
#define NEG 0.2f
#define EPS_SM 1e-16f
#define EPS_BN 1e-5f
#define FULLM 0xffffffffu
#define NEG_BIG (-1e30f)

// ---------------- scratch ----------------
// message storage: fp16, layout [n][c_pair(32)][head(4)] as half2 -> one
// LDG.128 per lane fetches (4 heads x 2 channels); warp reads 512B contiguous.
__device__ __half2 g_hh[NN * 128];
__device__ float g_al[NN * HH];     // attn src terms (atomic-accumulated by GEMM)
__device__ float g_ar[NN * HH];
__device__ float g_acc[NN * CC];    // aggregation output / next-layer input
__device__ float g_bn[2 * CC];      // [0:64) sum, [64:128) sumsq
__device__ float g_scale[CC];       // BN folded scale
__device__ float g_shift[CC];       // BN folded shift
__device__ __half g_Bhi[256 * 256]; // pre-split weight matrix (hi)
__device__ __half g_Blo[256 * 256]; // pre-split weight matrix (lo)
__device__ int   g_deg[NN];
__device__ int   g_off[NN + 1];
__device__ int   g_cur[NN];
__device__ int   g_srcid[ET];       // CSR (by dst) source node ids

__device__ __forceinline__ float lrelu(float v) { return v > 0.f ? v : NEG * v; }

__device__ __forceinline__ unsigned sptr(const void* p) {
    return (unsigned)__cvta_generic_to_shared(p);
}

__device__ __forceinline__ unsigned pack2h(float a, float b) {
    __half2 h = __floats2half2_rn(a, b);
    return reinterpret_cast<unsigned&>(h);
}

// ================= CSR build (once per launch) =================
__global__ void hist_kernel(const int* __restrict__ ei)
{
    int e = blockIdx.x * blockDim.x + threadIdx.x;
    if (e < EE) atomicAdd(&g_deg[ei[EE + e]], 1);
}

// single-block scan, coalesced chunked version: 49 chunks of 1024, block-wide
// inclusive scan per chunk + running carry. Self-loop (+1) folded in.
__global__ __launch_bounds__(1024) void scan_kernel()
{
    __shared__ int wsum[32];
    const int t = threadIdx.x;
    const int lane = t & 31, w = t >> 5;
    int carry = 0;
    const int NCHUNK = (NN + 1023) / 1024;   // 49
    for (int c = 0; c < NCHUNK; c++) {
        int idx = c * 1024 + t;
        int d = (idx < NN) ? g_deg[idx] + 1 : 0;
        // warp inclusive scan
        int v = d;
#pragma unroll
        for (int o = 1; o < 32; o <<= 1) {
            int u = __shfl_up_sync(FULLM, v, o);
            if (lane >= o) v += u;
        }
        if (lane == 31) wsum[w] = v;
        __syncthreads();
        if (w == 0) {
            int ws = wsum[lane];
#pragma unroll
            for (int o = 1; o < 32; o <<= 1) {
                int u = __shfl_up_sync(FULLM, ws, o);
                if (lane >= o) ws += u;
            }
            wsum[lane] = ws;
        }
        __syncthreads();
        int excl = v - d + (w > 0 ? wsum[w - 1] : 0) + carry;
        if (idx < NN) {
            g_off[idx] = excl;
            g_srcid[excl] = idx;     // self loop occupies first slot
            g_cur[idx] = excl + 1;
        }
        carry += wsum[31];
        __syncthreads();
    }
    if (t == 0) g_off[NN] = ET;
}

__global__ void scatter_kernel(const int* __restrict__ ei)
{
    int e = blockIdx.x * blockDim.x + threadIdx.x;
    if (e >= EE) return;
    int s = ei[e], d = ei[EE + e];
    int pos = atomicAdd(&g_cur[d], 1);
    g_srcid[pos] = s;
}

// ================= B pre-split: fp32 -> (hi, lo) halves =================
__global__ void bsplit_kernel(const float* __restrict__ B, int n)
{
    int i = blockIdx.x * blockDim.x + threadIdx.x;
    if (i >= n) return;
    float v = B[i];
    __half hi = __float2half_rn(v);
    g_Bhi[i] = hi;
    g_Blo[i] = __float2half_rn(v - __half2float(hi));
}

// ================= tensor-core GEMM + fused BN(A) + fused attn epilogue ====
#define ASTR 40
#define BSTR 72

__device__ __forceinline__ void mma16816(float* c, const unsigned* a, const unsigned* b)
{
    asm volatile(
        "mma.sync.aligned.m16n8k16.row.col.f32.f16.f16.f32 "
        "{%0,%1,%2,%3}, {%4,%5,%6,%7}, {%8,%9}, {%0,%1,%2,%3};"
        : "+f"(c[0]), "+f"(c[1]), "+f"(c[2]), "+f"(c[3])
        : "r"(a[0]), "r"(a[1]), "r"(a[2]), "r"(a[3]), "r"(b[0]), "r"(b[1]));
}

__device__ __forceinline__ void ldm_x4(unsigned* r, unsigned addr)
{
    asm volatile("ldmatrix.sync.aligned.m8n8.x4.shared.b16 {%0,%1,%2,%3}, [%4];"
                 : "=r"(r[0]), "=r"(r[1]), "=r"(r[2]), "=r"(r[3]) : "r"(addr));
}

__device__ __forceinline__ void ldm_x2t(unsigned* r, unsigned addr)
{
    asm volatile("ldmatrix.sync.aligned.m8n8.x2.trans.shared.b16 {%0,%1}, [%2];"
                 : "=r"(r[0]), "=r"(r[1]) : "r"(addr));
}

template <int K, bool BN>
__global__ __launch_bounds__(256, 2) void mma_gemm_kernel(
    const float* __restrict__ A,
    const float* __restrict__ asrc, const float* __restrict__ adst)
{
    __shared__ __half As_hi[128][ASTR];
    __shared__ __half As_lo[128][ASTR];
    __shared__ __half Bs_hi[32][BSTR];
    __shared__ __half Bs_lo[32][BSTR];

    const int row0 = blockIdx.y * 128;
    const int bn0  = blockIdx.x * 64;
    const int tid  = threadIdx.x;
    const int lane = tid & 31;
    const int wid  = tid >> 5;
    const int warp_m = wid & 3;
    const int warp_n = wid >> 2;
    const int g  = lane >> 2;
    const int tq = lane & 3;

    float acc[2][4][4];
#pragma unroll
    for (int mi = 0; mi < 2; mi++)
#pragma unroll
        for (int ni = 0; ni < 4; ni++)
#pragma unroll
            for (int q = 0; q < 4; q++) acc[mi][ni][q] = 0.f;

    const int arw = tid >> 1;
    const int ac0 = (tid & 1) * 16;
    const int brw = tid >> 3;
    const int bc0 = (tid & 7) * 8;

    const int gr = row0 + arw;
    const bool ok = gr < NN;
    const float* ap = A + (size_t)gr * K + ac0;
    const __half* bhp = g_Bhi + (size_t)brw * 256 + bn0 + bc0;
    const __half* blp = g_Blo + (size_t)brw * 256 + bn0 + bc0;
    const float4 zero4 = make_float4(0.f, 0.f, 0.f, 0.f);

    float4 af[4];
    uint4 bh, bl;
#pragma unroll
    for (int v = 0; v < 4; v++)
        af[v] = ok ? *(const float4*)(ap + v * 4) : zero4;
    bh = *(const uint4*)bhp;
    bl = *(const uint4*)blp;

    for (int k0 = 0; k0 < K; k0 += 32) {
        if (k0) __syncthreads();

        {
            float val[16];
#pragma unroll
            for (int v = 0; v < 4; v++) {
                val[v * 4 + 0] = af[v].x;
                val[v * 4 + 1] = af[v].y;
                val[v * 4 + 2] = af[v].z;
                val[v * 4 + 3] = af[v].w;
            }
            if (BN && ok) {
#pragma unroll
                for (int i = 0; i < 16; i++) {
                    int c = k0 + ac0 + i;
                    val[i] = fmaxf(fmaf(val[i], g_scale[c], g_shift[c]), 0.f);
                }
            }
            float lo[16];
#pragma unroll
            for (int i = 0; i < 16; i++)
                lo[i] = val[i] - __half2float(__float2half_rn(val[i]));
            uint4 uh0, uh1, ul0, ul1;
            uh0.x = pack2h(val[0], val[1]);   uh0.y = pack2h(val[2], val[3]);
            uh0.z = pack2h(val[4], val[5]);   uh0.w = pack2h(val[6], val[7]);
            uh1.x = pack2h(val[8], val[9]);   uh1.y = pack2h(val[10], val[11]);
            uh1.z = pack2h(val[12], val[13]); uh1.w = pack2h(val[14], val[15]);
            ul0.x = pack2h(lo[0], lo[1]);     ul0.y = pack2h(lo[2], lo[3]);
            ul0.z = pack2h(lo[4], lo[5]);     ul0.w = pack2h(lo[6], lo[7]);
            ul1.x = pack2h(lo[8], lo[9]);     ul1.y = pack2h(lo[10], lo[11]);
            ul1.z = pack2h(lo[12], lo[13]);   ul1.w = pack2h(lo[14], lo[15]);
            *(uint4*)&As_hi[arw][ac0]     = uh0;
            *(uint4*)&As_hi[arw][ac0 + 8] = uh1;
            *(uint4*)&As_lo[arw][ac0]     = ul0;
            *(uint4*)&As_lo[arw][ac0 + 8] = ul1;
            *(uint4*)&Bs_hi[brw][bc0] = bh;
            *(uint4*)&Bs_lo[brw][bc0] = bl;
        }
        __syncthreads();

        if (k0 + 32 < K) {
            const int kn = k0 + 32;
#pragma unroll
            for (int v = 0; v < 4; v++)
                af[v] = ok ? *(const float4*)(ap + kn + v * 4) : zero4;
            bh = *(const uint4*)(bhp + (size_t)kn * 256);
            bl = *(const uint4*)(blp + (size_t)kn * 256);
        }

#pragma unroll
        for (int ks = 0; ks < 2; ks++) {
            unsigned ahi[2][4], alo[2][4], bhi[4][2], blo[4][2];
#pragma unroll
            for (int mi = 0; mi < 2; mi++) {
                int r = warp_m * 32 + mi * 16 + (lane & 15);
                int c = ks * 16 + (lane >> 4) * 8;
                ldm_x4(ahi[mi], sptr(&As_hi[r][c]));
                ldm_x4(alo[mi], sptr(&As_lo[r][c]));
            }
#pragma unroll
            for (int ni = 0; ni < 4; ni++) {
                int r = ks * 16 + (lane & 15);
                int c = warp_n * 32 + ni * 8;
                ldm_x2t(bhi[ni], sptr(&Bs_hi[r][c]));
                ldm_x2t(blo[ni], sptr(&Bs_lo[r][c]));
            }
#pragma unroll
            for (int mi = 0; mi < 2; mi++)
#pragma unroll
                for (int ni = 0; ni < 4; ni++) {
                    mma16816(acc[mi][ni], ahi[mi], bhi[ni]);
                    mma16816(acc[mi][ni], ahi[mi], blo[ni]);
                    mma16816(acc[mi][ni], alo[mi], bhi[ni]);
                }
        }
    }

    // ---- epilogue 1: write fp16 messages to g_hh[n][c_pair][head] ----
    {
        const int h = blockIdx.x;
#pragma unroll
        for (int mi = 0; mi < 2; mi++) {
            int r = row0 + warp_m * 32 + mi * 16 + g;
#pragma unroll
            for (int ni = 0; ni < 4; ni++) {
                int cp = warp_n * 16 + ni * 4 + tq;     // channel pair 0..31
                if (r < NN)
                    g_hh[(size_t)r * 128 + cp * 4 + h] =
                        __floats2half2_rn(acc[mi][ni][0], acc[mi][ni][1]);
                if (r + 8 < NN)
                    g_hh[(size_t)(r + 8) * 128 + cp * 4 + h] =
                        __floats2half2_rn(acc[mi][ni][2], acc[mi][ni][3]);
            }
        }
    }

    // ---- epilogue 2: fused attention coefficients for head = blockIdx.x ----
    {
        const int h = blockIdx.x;
        const float* asb = asrc + h * CC;
        const float* adb = adst + h * CC;
        float sl[2][2] = {{0.f, 0.f}, {0.f, 0.f}};
        float sr[2][2] = {{0.f, 0.f}, {0.f, 0.f}};
#pragma unroll
        for (int mi = 0; mi < 2; mi++)
#pragma unroll
            for (int ni = 0; ni < 4; ni++)
#pragma unroll
                for (int q = 0; q < 4; q++) {
                    int cl = warp_n * 32 + ni * 8 + 2 * tq + (q & 1);
                    float v = acc[mi][ni][q];
                    sl[mi][q >> 1] = fmaf(v, asb[cl], sl[mi][q >> 1]);
                    sr[mi][q >> 1] = fmaf(v, adb[cl], sr[mi][q >> 1]);
                }
#pragma unroll
        for (int mi = 0; mi < 2; mi++)
#pragma unroll
            for (int hf = 0; hf < 2; hf++) {
                float a = sl[mi][hf], b = sr[mi][hf];
                a += __shfl_xor_sync(FULLM, a, 1);
                a += __shfl_xor_sync(FULLM, a, 2);
                b += __shfl_xor_sync(FULLM, b, 1);
                b += __shfl_xor_sync(FULLM, b, 2);
                int r = row0 + warp_m * 32 + mi * 16 + g + hf * 8;
                if (tq == 0 && r < NN) {
                    atomicAdd(&g_al[r * 4 + h], a);
                    atomicAdd(&g_ar[r * 4 + h], b);
                }
            }
    }
}

// ================= fused softmax + aggregation: warp per dst node ==========
// Pass 2 uses smem-broadcast weights (no shfl) and 4-way unrolled gathers
// (MLP=4) to hide L2 latency.
template <bool FINAL>
__global__ __launch_bounds__(256) void node_kernel(
    float* __restrict__ out, const float* __restrict__ bias)
{
    __shared__ float sbn[2 * CC];
    __shared__ float4 s_w[8][32];
    __shared__ int    s_sid[8][32];
    if (!FINAL) {
        if (threadIdx.x < 2 * CC) sbn[threadIdx.x] = 0.f;
        __syncthreads();
    }

    const int d    = blockIdx.x * 8 + (threadIdx.x >> 5);
    const int ws   = threadIdx.x >> 5;
    const int lane = threadIdx.x & 31;
    const int start = g_off[d];
    const int end   = g_off[d + 1];
    const float4 ar = *(const float4*)(g_ar + 4 * d);

    // pass 1: online softmax per head (finite sentinel avoids NaN on empty lanes)
    float m0 = NEG_BIG, m1 = NEG_BIG, m2 = NEG_BIG, m3 = NEG_BIG;
    float s0 = 0.f, s1 = 0.f, s2 = 0.f, s3 = 0.f;
    for (int sl = start + lane; sl < end; sl += 32) {
        int s = g_srcid[sl];
        float4 al = *(const float4*)(g_al + 4 * s);
        float e0 = lrelu(al.x + ar.x);
        float e1 = lrelu(al.y + ar.y);
        float e2 = lrelu(al.z + ar.z);
        float e3 = lrelu(al.w + ar.w);
        float mn;
        mn = fmaxf(m0, e0); s0 = s0 * __expf(m0 - mn) + __expf(e0 - mn); m0 = mn;
        mn = fmaxf(m1, e1); s1 = s1 * __expf(m1 - mn) + __expf(e1 - mn); m1 = mn;
        mn = fmaxf(m2, e2); s2 = s2 * __expf(m2 - mn) + __expf(e2 - mn); m2 = mn;
        mn = fmaxf(m3, e3); s3 = s3 * __expf(m3 - mn) + __expf(e3 - mn); m3 = mn;
    }
#pragma unroll
    for (int o = 16; o; o >>= 1) {
        float mo, so, mn;
        mo = __shfl_xor_sync(FULLM, m0, o); so = __shfl_xor_sync(FULLM, s0, o);
        mn = fmaxf(m0, mo); s0 = s0 * __expf(m0 - mn) + so * __expf(mo - mn); m0 = mn;
        mo = __shfl_xor_sync(FULLM, m1, o); so = __shfl_xor_sync(FULLM, s1, o);
        mn = fmaxf(m1, mo); s1 = s1 * __expf(m1 - mn) + so * __expf(mo - mn); m1 = mn;
        mo = __shfl_xor_sync(FULLM, m2, o); so = __shfl_xor_sync(FULLM, s2, o);
        mn = fmaxf(m2, mo); s2 = s2 * __expf(m2 - mn) + so * __expf(mo - mn); m2 = mn;
        mo = __shfl_xor_sync(FULLM, m3, o); so = __shfl_xor_sync(FULLM, s3, o);
        mn = fmaxf(m3, mo); s3 = s3 * __expf(m3 - mn) + so * __expf(mo - mn); m3 = mn;
    }
    const float i0 = 0.25f / (s0 + EPS_SM);
    const float i1 = 0.25f / (s1 + EPS_SM);
    const float i2 = 0.25f / (s2 + EPS_SM);
    const float i3 = 0.25f / (s3 + EPS_SM);

    // pass 2: smem-staged weights, 4-way unrolled gather (4 LDG.128 in flight)
    float accx = 0.f, accy = 0.f;
    const __half2* hrow = g_hh + (size_t)lane * 4;
    for (int base = start; base < end; base += 32) {
        int sl = base + lane;
        int sid = 0;
        float w0 = 0.f, w1 = 0.f, w2 = 0.f, w3 = 0.f;
        if (sl < end) {
            sid = g_srcid[sl];
            float4 al = *(const float4*)(g_al + 4 * sid);
            w0 = __expf(lrelu(al.x + ar.x) - m0) * i0;
            w1 = __expf(lrelu(al.y + ar.y) - m1) * i1;
            w2 = __expf(lrelu(al.z + ar.z) - m2) * i2;
            w3 = __expf(lrelu(al.w + ar.w) - m3) * i3;
        }
        s_w[ws][lane] = make_float4(w0, w1, w2, w3);
        s_sid[ws][lane] = sid;
        __syncwarp();
        const int cnt = min(32, end - base);
        int j = 0;
        for (; j + 4 <= cnt; j += 4) {
            int sjA = s_sid[ws][j],     sjB = s_sid[ws][j + 1];
            int sjC = s_sid[ws][j + 2], sjD = s_sid[ws][j + 3];
            float4 uA = s_w[ws][j],     uB = s_w[ws][j + 1];
            float4 uC = s_w[ws][j + 2], uD = s_w[ws][j + 3];
            uint4 rA = *(const uint4*)(hrow + (size_t)sjA * 128);
            uint4 rB = *(const uint4*)(hrow + (size_t)sjB * 128);
            uint4 rC = *(const uint4*)(hrow + (size_t)sjC * 128);
            uint4 rD = *(const uint4*)(hrow + (size_t)sjD * 128);
            {
                const __half2* hv = (const __half2*)&rA;
                float2 f0 = __half22float2(hv[0]), f1 = __half22float2(hv[1]);
                float2 f2 = __half22float2(hv[2]), f3 = __half22float2(hv[3]);
                accx += f0.x * uA.x + f1.x * uA.y + f2.x * uA.z + f3.x * uA.w;
                accy += f0.y * uA.x + f1.y * uA.y + f2.y * uA.z + f3.y * uA.w;
            }
            {
                const __half2* hv = (const __half2*)&rB;
                float2 f0 = __half22float2(hv[0]), f1 = __half22float2(hv[1]);
                float2 f2 = __half22float2(hv[2]), f3 = __half22float2(hv[3]);
                accx += f0.x * uB.x + f1.x * uB.y + f2.x * uB.z + f3.x * uB.w;
                accy += f0.y * uB.x + f1.y * uB.y + f2.y * uB.z + f3.y * uB.w;
            }
            {
                const __half2* hv = (const __half2*)&rC;
                float2 f0 = __half22float2(hv[0]), f1 = __half22float2(hv[1]);
                float2 f2 = __half22float2(hv[2]), f3 = __half22float2(hv[3]);
                accx += f0.x * uC.x + f1.x * uC.y + f2.x * uC.z + f3.x * uC.w;
                accy += f0.y * uC.x + f1.y * uC.y + f2.y * uC.z + f3.y * uC.w;
            }
            {
                const __half2* hv = (const __half2*)&rD;
                float2 f0 = __half22float2(hv[0]), f1 = __half22float2(hv[1]);
                float2 f2 = __half22float2(hv[2]), f3 = __half22float2(hv[3]);
                accx += f0.x * uD.x + f1.x * uD.y + f2.x * uD.z + f3.x * uD.w;
                accy += f0.y * uD.x + f1.y * uD.y + f2.y * uD.z + f3.y * uD.w;
            }
        }
        for (; j < cnt; j++) {
            int sj = s_sid[ws][j];
            float4 u = s_w[ws][j];
            uint4 r = *(const uint4*)(hrow + (size_t)sj * 128);
            const __half2* hv = (const __half2*)&r;
            float2 f0 = __half22float2(hv[0]), f1 = __half22float2(hv[1]);
            float2 f2 = __half22float2(hv[2]), f3 = __half22float2(hv[3]);
            accx += f0.x * u.x + f1.x * u.y + f2.x * u.z + f3.x * u.w;
            accy += f0.y * u.x + f1.y * u.y + f2.y * u.z + f3.y * u.w;
        }
        __syncwarp();
    }

    const int c2 = 2 * lane;
    if (FINAL) {
        float2 bv = *(const float2*)&bias[c2];
        *(float2*)&out[(size_t)d * CC + c2] = make_float2(accx + bv.x, accy + bv.y);
    } else {
        *(float2*)&out[(size_t)d * CC + c2] = make_float2(accx, accy);
        atomicAdd(&sbn[c2],          accx);
        atomicAdd(&sbn[c2 + 1],      accy);
        atomicAdd(&sbn[64 + c2],     accx * accx);
        atomicAdd(&sbn[64 + c2 + 1], accy * accy);
        __syncthreads();
        if (threadIdx.x < 2 * CC) atomicAdd(&g_bn[threadIdx.x], sbn[threadIdx.x]);
    }
}

// ================= BN fold: stats -> per-channel scale/shift =================
__global__ void bn_prep_kernel(const float* __restrict__ gam,
                               const float* __restrict__ bet)
{
    int c = threadIdx.x;
    if (c >= CC) return;
    const float inv_n = 1.f / (float)NN;
    float mu = g_bn[c] * inv_n;
    float var = g_bn[64 + c] * inv_n - mu * mu;
    float s = rsqrtf(var + EPS_BN) * gam[c];
    g_scale[c] = s;
    g_shift[c] = bet[c] - mu * s;
}

// ================= host orchestration =================
extern "C" void kernel_launch(void* const* d_in, const int* in_sizes, int n_in,
                              void* d_out, int out_size)
{
    const float* x   = (const float*)d_in[0];
    const int*   ei  = (const int*)d_in[1];
    const float* W0  = (const float*)d_in[2];
    const float* as0 = (const float*)d_in[3];
    const float* ad0 = (const float*)d_in[4];
    const float* W1  = (const float*)d_in[6];
    const float* as1 = (const float*)d_in[7];
    const float* ad1 = (const float*)d_in[8];
    const float* W2  = (const float*)d_in[10];
    const float* as2 = (const float*)d_in[11];
    const float* ad2 = (const float*)d_in[12];
    const float* b2  = (const float*)d_in[13];
    const float* g0  = (const float*)d_in[14];
    const float* be0 = (const float*)d_in[15];
    const float* g1  = (const float*)d_in[16];
    const float* be1 = (const float*)d_in[17];
    float* out = (float*)d_out;

    float *acc_ptr, *bn_ptr, *al_ptr, *ar_ptr;
    int *deg_ptr;
    cudaGetSymbolAddress((void**)&acc_ptr, g_acc);
    cudaGetSymbolAddress((void**)&bn_ptr, g_bn);
    cudaGetSymbolAddress((void**)&al_ptr, g_al);
    cudaGetSymbolAddress((void**)&ar_ptr, g_ar);
    cudaGetSymbolAddress((void**)&deg_ptr, g_deg);

    const dim3 gemm_grid(4, (NN + 127) / 128);
    const int node_blocks = NN / 8;
    const int edge_blocks = (EE + 255) / 256;
    const size_t attn_bytes = (size_t)NN * HH * sizeof(float);

    // ---- CSR build (edge structure is layer-invariant) ----
    cudaMemsetAsync(deg_ptr, 0, NN * sizeof(int));
    hist_kernel<<<edge_blocks, 256>>>(ei);
    scan_kernel<<<1, 1024>>>();
    scatter_kernel<<<edge_blocks, 256>>>(ei);

    // ---- layer 0 ----
    cudaMemsetAsync(al_ptr, 0, attn_bytes);
    cudaMemsetAsync(ar_ptr, 0, attn_bytes);
    cudaMemsetAsync(bn_ptr, 0, 2 * CC * sizeof(float));
    bsplit_kernel<<<(256 * 256 + 255) / 256, 256>>>(W0, 256 * 256);
    mma_gemm_kernel<256, false><<<gemm_grid, 256>>>(x, as0, ad0);
    node_kernel<false><<<node_blocks, 256>>>(acc_ptr, nullptr);
    bn_prep_kernel<<<1, 64>>>(g0, be0);

    // ---- layer 1 ----
    cudaMemsetAsync(al_ptr, 0, attn_bytes);
    cudaMemsetAsync(ar_ptr, 0, attn_bytes);
    cudaMemsetAsync(bn_ptr, 0, 2 * CC * sizeof(float));
    bsplit_kernel<<<(64 * 256 + 255) / 256, 256>>>(W1, 64 * 256);
    mma_gemm_kernel<64, true><<<gemm_grid, 256>>>(acc_ptr, as1, ad1);
    node_kernel<false><<<node_blocks, 256>>>(acc_ptr, nullptr);
    bn_prep_kernel<<<1, 64>>>(g1, be1);

    // ---- layer 2 ----
    cudaMemsetAsync(al_ptr, 0, attn_bytes);
    cudaMemsetAsync(ar_ptr, 0, attn_bytes);
    bsplit_kernel<<<(64 * 256 + 255) / 256, 256>>>(W2, 64 * 256);
    mma_gemm_kernel<64, true><<<gemm_grid, 256>>>(acc_ptr, as2, ad2);
    node_kernel<true><<<node_blocks, 256>>>(out, b2);
}